// round 1
// baseline (speedup 1.0000x reference)
#include <cuda_runtime.h>
#include <math.h>

#define B_SZ   8
#define N_TOK  2048
#define C_DIM  256
#define H_NUM  8
#define D_HEAD 32
#define HID_D  1024
#define M_ROWS (B_SZ * N_TOK)            /* 16384 */
#define BHND   (B_SZ * H_NUM * N_TOK * D_HEAD) /* 4194304 */

// Scratch (allocation-free: device globals)
__device__ float g_xln[(size_t)M_ROWS * C_DIM];
__device__ float g_qkv[(size_t)3 * BHND];
__device__ float g_attn[(size_t)M_ROWS * C_DIM];
__device__ float g_h[(size_t)M_ROWS * HID_D];

// ---------------------------------------------------------------------------
// LayerNorm: one warp per row of 256, blockDim (32, 8)
// ---------------------------------------------------------------------------
__global__ __launch_bounds__(256) void ln_kernel(
    const float* __restrict__ x, const float* __restrict__ g,
    const float* __restrict__ b, float* __restrict__ out)
{
    int row  = blockIdx.x * 8 + threadIdx.y;
    int lane = threadIdx.x;
    const float* xr = x + (size_t)row * C_DIM;

    float4 v0 = *reinterpret_cast<const float4*>(xr + lane * 4);
    float4 v1 = *reinterpret_cast<const float4*>(xr + 128 + lane * 4);

    float s  = v0.x + v0.y + v0.z + v0.w + v1.x + v1.y + v1.z + v1.w;
    float sq = v0.x*v0.x + v0.y*v0.y + v0.z*v0.z + v0.w*v0.w
             + v1.x*v1.x + v1.y*v1.y + v1.z*v1.z + v1.w*v1.w;

    #pragma unroll
    for (int off = 16; off > 0; off >>= 1) {
        s  += __shfl_xor_sync(0xffffffffu, s,  off);
        sq += __shfl_xor_sync(0xffffffffu, sq, off);
    }
    float mean = s * (1.0f / 256.0f);
    float var  = sq * (1.0f / 256.0f) - mean * mean;
    float rstd = rsqrtf(var + 1e-5f);

    float4 g0 = *reinterpret_cast<const float4*>(g + lane * 4);
    float4 g1 = *reinterpret_cast<const float4*>(g + 128 + lane * 4);
    float4 b0 = *reinterpret_cast<const float4*>(b + lane * 4);
    float4 b1 = *reinterpret_cast<const float4*>(b + 128 + lane * 4);

    float4 o0, o1;
    o0.x = (v0.x - mean) * rstd * g0.x + b0.x;
    o0.y = (v0.y - mean) * rstd * g0.y + b0.y;
    o0.z = (v0.z - mean) * rstd * g0.z + b0.z;
    o0.w = (v0.w - mean) * rstd * g0.w + b0.w;
    o1.x = (v1.x - mean) * rstd * g1.x + b1.x;
    o1.y = (v1.y - mean) * rstd * g1.y + b1.y;
    o1.z = (v1.z - mean) * rstd * g1.z + b1.z;
    o1.w = (v1.w - mean) * rstd * g1.w + b1.w;

    float* orow = out + (size_t)row * C_DIM;
    *reinterpret_cast<float4*>(orow + lane * 4)       = o0;
    *reinterpret_cast<float4*>(orow + 128 + lane * 4) = o1;
}

// ---------------------------------------------------------------------------
// GEMM: C[M,Nn] = A[M,K] @ W[Nn,K]^T  (torch Linear layout)
// 64x64 tile, BK=32, 256 threads, 4x4 microtile.
// Epilogues: 0 = QKV scatter, 1 = +bias +residual, 2 = +bias +exact GELU
// ---------------------------------------------------------------------------
#define EPI_QKV      0
#define EPI_BIAS_RES 1
#define EPI_GELU     2

template<int EPI>
__global__ __launch_bounds__(256) void gemm_kernel(
    const float* __restrict__ A, const float* __restrict__ W,
    const float* __restrict__ bias, const float* __restrict__ res,
    float* __restrict__ out, int Mr, int Nn, int K)
{
    __shared__ float As[32][68];
    __shared__ float Ws[32][68];

    int tid = threadIdx.x;
    int tx = tid & 15, ty = tid >> 4;
    int m0 = blockIdx.y * 64, n0 = blockIdx.x * 64;

    float acc[4][4] = {};

    for (int k0 = 0; k0 < K; k0 += 32) {
        #pragma unroll
        for (int r = 0; r < 2; r++) {
            int f = tid + r * 256;
            int row = f >> 3, seg = f & 7;
            float4 av = *reinterpret_cast<const float4*>(
                A + (size_t)(m0 + row) * K + k0 + seg * 4);
            As[seg*4 + 0][row] = av.x; As[seg*4 + 1][row] = av.y;
            As[seg*4 + 2][row] = av.z; As[seg*4 + 3][row] = av.w;
            float4 wv = *reinterpret_cast<const float4*>(
                W + (size_t)(n0 + row) * K + k0 + seg * 4);
            Ws[seg*4 + 0][row] = wv.x; Ws[seg*4 + 1][row] = wv.y;
            Ws[seg*4 + 2][row] = wv.z; Ws[seg*4 + 3][row] = wv.w;
        }
        __syncthreads();

        #pragma unroll
        for (int kk = 0; kk < 32; kk++) {
            float4 a4 = *reinterpret_cast<const float4*>(&As[kk][ty * 4]);
            float4 w4 = *reinterpret_cast<const float4*>(&Ws[kk][tx * 4]);
            float av[4] = {a4.x, a4.y, a4.z, a4.w};
            float wv[4] = {w4.x, w4.y, w4.z, w4.w};
            #pragma unroll
            for (int i = 0; i < 4; i++)
                #pragma unroll
                for (int j = 0; j < 4; j++)
                    acc[i][j] += av[i] * wv[j];
        }
        __syncthreads();
    }

    #pragma unroll
    for (int i = 0; i < 4; i++) {
        int m = m0 + ty * 4 + i;
        #pragma unroll
        for (int j = 0; j < 4; j++) {
            int o = n0 + tx * 4 + j;
            float v = acc[i][j];
            if (EPI == EPI_QKV) {
                // o -> (part, h, d); m -> (b, n); dst layout (3,B,H,N,D)
                int part = o >> 8;
                int rem  = o & 255;
                int h    = rem >> 5;
                int d    = rem & 31;
                int bb   = m >> 11;
                int n    = m & 2047;
                out[(size_t)part * BHND +
                    ((size_t)(bb * H_NUM + h) * N_TOK + n) * D_HEAD + d] = v;
            } else if (EPI == EPI_BIAS_RES) {
                size_t idx = (size_t)m * Nn + o;
                out[idx] = v + bias[o] + res[idx];
            } else { // EPI_GELU
                v += bias[o];
                out[(size_t)m * Nn + o] = 0.5f * v * (1.0f + erff(v * 0.70710678f));
            }
        }
    }
}

// ---------------------------------------------------------------------------
// Attention: flash-style, one pass (scores tiny -> exp without max shift).
// Grid (N/64, B*H), 256 threads. Q tile 64x32, stream KV in 64-row tiles.
// Diagonal masked to exact zero probability.
// ---------------------------------------------------------------------------
__global__ __launch_bounds__(256) void attn_kernel(
    const float* __restrict__ Qg, const float* __restrict__ Kg,
    const float* __restrict__ Vg, const float* __restrict__ scale_p,
    float* __restrict__ Outg)
{
    __shared__ float Qs[32][68];  // d-major, float4 friendly
    __shared__ float Ks[32][68];
    __shared__ float Vs[64][34];  // row-major, float2 friendly
    __shared__ float Ps[64][65];

    int tid = threadIdx.x;
    int tx = tid & 15, ty = tid >> 4;
    int bh = blockIdx.y;
    int q0 = blockIdx.x * 64;
    const float scale = *scale_p;

    const float* Qb = Qg + (size_t)bh * N_TOK * D_HEAD;
    const float* Kb = Kg + (size_t)bh * N_TOK * D_HEAD;
    const float* Vb = Vg + (size_t)bh * N_TOK * D_HEAD;

    // Load Q tile (transposed to d-major)
    #pragma unroll
    for (int r = 0; r < 2; r++) {
        int f = tid + r * 256;
        int row = f >> 3, seg = f & 7;
        float4 qv = *reinterpret_cast<const float4*>(Qb + (size_t)(q0 + row) * 32 + seg * 4);
        Qs[seg*4 + 0][row] = qv.x; Qs[seg*4 + 1][row] = qv.y;
        Qs[seg*4 + 2][row] = qv.z; Qs[seg*4 + 3][row] = qv.w;
    }

    float o_acc[4][2] = {};
    float l_acc[4]    = {};

    for (int t0 = 0; t0 < N_TOK; t0 += 64) {
        __syncthreads();  // protect Ks/Vs/Ps from previous iteration readers
        #pragma unroll
        for (int r = 0; r < 2; r++) {
            int f = tid + r * 256;
            int row = f >> 3, seg = f & 7;
            float4 kv = *reinterpret_cast<const float4*>(Kb + (size_t)(t0 + row) * 32 + seg * 4);
            Ks[seg*4 + 0][row] = kv.x; Ks[seg*4 + 1][row] = kv.y;
            Ks[seg*4 + 2][row] = kv.z; Ks[seg*4 + 3][row] = kv.w;
            float4 vv = *reinterpret_cast<const float4*>(Vb + (size_t)(t0 + row) * 32 + seg * 4);
            Vs[row][seg*4 + 0] = vv.x; Vs[row][seg*4 + 1] = vv.y;
            Vs[row][seg*4 + 2] = vv.z; Vs[row][seg*4 + 3] = vv.w;
        }
        __syncthreads();

        // S = Q K^T (4x4 per thread)
        float s[4][4] = {};
        #pragma unroll
        for (int d = 0; d < 32; d++) {
            float4 q4 = *reinterpret_cast<const float4*>(&Qs[d][ty * 4]);
            float4 k4 = *reinterpret_cast<const float4*>(&Ks[d][tx * 4]);
            float qv[4] = {q4.x, q4.y, q4.z, q4.w};
            float kv[4] = {k4.x, k4.y, k4.z, k4.w};
            #pragma unroll
            for (int i = 0; i < 4; i++)
                #pragma unroll
                for (int j = 0; j < 4; j++)
                    s[i][j] += qv[i] * kv[j];
        }

        // exp + diagonal mask + row-sum partials
        #pragma unroll
        for (int i = 0; i < 4; i++) {
            int qi = q0 + ty * 4 + i;
            #pragma unroll
            for (int j = 0; j < 4; j++) {
                int kj = t0 + tx * 4 + j;
                float e = (qi == kj) ? 0.0f : __expf(s[i][j] * scale);
                Ps[ty*4 + i][tx*4 + j] = e;
                l_acc[i] += e;
            }
        }
        __syncthreads();

        // O += P V  (4 rows x 2 cols per thread)
        #pragma unroll 16
        for (int j = 0; j < 64; j++) {
            float p0 = Ps[ty*4 + 0][j];
            float p1 = Ps[ty*4 + 1][j];
            float p2 = Ps[ty*4 + 2][j];
            float p3 = Ps[ty*4 + 3][j];
            float2 v2 = *reinterpret_cast<const float2*>(&Vs[j][tx * 2]);
            o_acc[0][0] += p0 * v2.x; o_acc[0][1] += p0 * v2.y;
            o_acc[1][0] += p1 * v2.x; o_acc[1][1] += p1 * v2.y;
            o_acc[2][0] += p2 * v2.x; o_acc[2][1] += p2 * v2.y;
            o_acc[3][0] += p3 * v2.x; o_acc[3][1] += p3 * v2.y;
        }
    }

    // reduce l across the 16 tx threads (lane bits 0..3)
    #pragma unroll
    for (int i = 0; i < 4; i++) {
        #pragma unroll
        for (int off = 1; off < 16; off <<= 1)
            l_acc[i] += __shfl_xor_sync(0xffffffffu, l_acc[i], off);
    }

    int bb = bh >> 3, h = bh & 7;
    #pragma unroll
    for (int i = 0; i < 4; i++) {
        float inv = 1.0f / l_acc[i];
        int n = q0 + ty * 4 + i;
        size_t base = ((size_t)(bb * N_TOK + n)) * C_DIM + h * D_HEAD + tx * 2;
        Outg[base]     = o_acc[i][0] * inv;
        Outg[base + 1] = o_acc[i][1] * inv;
    }
}

// ---------------------------------------------------------------------------
extern "C" void kernel_launch(void* const* d_in, const int* in_sizes, int n_in,
                              void* d_out, int out_size)
{
    const float* x      = (const float*)d_in[0];
    const float* ln1_g  = (const float*)d_in[1];
    const float* ln1_b  = (const float*)d_in[2];
    const float* qkv_w  = (const float*)d_in[3];
    const float* scale  = (const float*)d_in[4];
    const float* proj_w = (const float*)d_in[5];
    const float* proj_b = (const float*)d_in[6];
    const float* ln2_g  = (const float*)d_in[7];
    const float* ln2_b  = (const float*)d_in[8];
    const float* fc1_w  = (const float*)d_in[9];
    const float* fc1_b  = (const float*)d_in[10];
    const float* fc2_w  = (const float*)d_in[11];
    const float* fc2_b  = (const float*)d_in[12];
    float* out = (float*)d_out;

    float *p_xln, *p_qkv, *p_attn, *p_h;
    cudaGetSymbolAddress((void**)&p_xln,  g_xln);
    cudaGetSymbolAddress((void**)&p_qkv,  g_qkv);
    cudaGetSymbolAddress((void**)&p_attn, g_attn);
    cudaGetSymbolAddress((void**)&p_h,    g_h);

    dim3 lnBlock(32, 8);

    // 1. LN1
    ln_kernel<<<M_ROWS / 8, lnBlock>>>(x, ln1_g, ln1_b, p_xln);

    // 2. QKV projection with scatter to (3,B,H,N,D)
    gemm_kernel<EPI_QKV><<<dim3(768 / 64, M_ROWS / 64), 256>>>(
        p_xln, qkv_w, nullptr, nullptr, p_qkv, M_ROWS, 768, C_DIM);

    // 3. Attention
    attn_kernel<<<dim3(N_TOK / 64, B_SZ * H_NUM), 256>>>(
        p_qkv, p_qkv + BHND, p_qkv + 2 * (size_t)BHND, scale, p_attn);

    // 4. proj + bias + residual -> out (= x after attention)
    gemm_kernel<EPI_BIAS_RES><<<dim3(C_DIM / 64, M_ROWS / 64), 256>>>(
        p_attn, proj_w, proj_b, x, out, M_ROWS, C_DIM, C_DIM);

    // 5. LN2
    ln_kernel<<<M_ROWS / 8, lnBlock>>>(out, ln2_g, ln2_b, p_xln);

    // 6. fc1 + bias + exact GELU
    gemm_kernel<EPI_GELU><<<dim3(HID_D / 64, M_ROWS / 64), 256>>>(
        p_xln, fc1_w, fc1_b, nullptr, p_h, M_ROWS, HID_D, C_DIM);

    // 7. fc2 + bias + residual -> out
    gemm_kernel<EPI_BIAS_RES><<<dim3(C_DIM / 64, M_ROWS / 64), 256>>>(
        p_h, fc2_w, fc2_b, out, out, M_ROWS, C_DIM, HID_D);
}

// round 2
// speedup vs baseline: 1.2316x; 1.2316x over previous
#include <cuda_runtime.h>
#include <math.h>

#define B_SZ   8
#define N_TOK  2048
#define C_DIM  256
#define H_NUM  8
#define D_HEAD 32
#define HID_D  1024
#define M_ROWS (B_SZ * N_TOK)            /* 16384 */
#define BHND   (B_SZ * H_NUM * N_TOK * D_HEAD) /* 4194304 */

// Scratch (allocation-free: device globals)
__device__ float g_xln[(size_t)M_ROWS * C_DIM];
__device__ float g_qkv[(size_t)3 * BHND];
__device__ float g_attn[(size_t)M_ROWS * C_DIM];
__device__ float g_h[(size_t)M_ROWS * HID_D];

// ---------------------------------------------------------------------------
// LayerNorm: one warp per row of 256, blockDim (32, 8)
// ---------------------------------------------------------------------------
__global__ __launch_bounds__(256) void ln_kernel(
    const float* __restrict__ x, const float* __restrict__ g,
    const float* __restrict__ b, float* __restrict__ out)
{
    int row  = blockIdx.x * 8 + threadIdx.y;
    int lane = threadIdx.x;
    const float* xr = x + (size_t)row * C_DIM;

    float4 v0 = *reinterpret_cast<const float4*>(xr + lane * 4);
    float4 v1 = *reinterpret_cast<const float4*>(xr + 128 + lane * 4);

    float s  = v0.x + v0.y + v0.z + v0.w + v1.x + v1.y + v1.z + v1.w;
    float sq = v0.x*v0.x + v0.y*v0.y + v0.z*v0.z + v0.w*v0.w
             + v1.x*v1.x + v1.y*v1.y + v1.z*v1.z + v1.w*v1.w;

    #pragma unroll
    for (int off = 16; off > 0; off >>= 1) {
        s  += __shfl_xor_sync(0xffffffffu, s,  off);
        sq += __shfl_xor_sync(0xffffffffu, sq, off);
    }
    float mean = s * (1.0f / 256.0f);
    float var  = sq * (1.0f / 256.0f) - mean * mean;
    float rstd = rsqrtf(var + 1e-5f);

    float4 g0 = *reinterpret_cast<const float4*>(g + lane * 4);
    float4 g1 = *reinterpret_cast<const float4*>(g + 128 + lane * 4);
    float4 b0 = *reinterpret_cast<const float4*>(b + lane * 4);
    float4 b1 = *reinterpret_cast<const float4*>(b + 128 + lane * 4);

    float4 o0, o1;
    o0.x = (v0.x - mean) * rstd * g0.x + b0.x;
    o0.y = (v0.y - mean) * rstd * g0.y + b0.y;
    o0.z = (v0.z - mean) * rstd * g0.z + b0.z;
    o0.w = (v0.w - mean) * rstd * g0.w + b0.w;
    o1.x = (v1.x - mean) * rstd * g1.x + b1.x;
    o1.y = (v1.y - mean) * rstd * g1.y + b1.y;
    o1.z = (v1.z - mean) * rstd * g1.z + b1.z;
    o1.w = (v1.w - mean) * rstd * g1.w + b1.w;

    float* orow = out + (size_t)row * C_DIM;
    *reinterpret_cast<float4*>(orow + lane * 4)       = o0;
    *reinterpret_cast<float4*>(orow + 128 + lane * 4) = o1;
}

// ---------------------------------------------------------------------------
// GEMM: C[M,Nn] = A[M,K] @ W[Nn,K]^T  (torch Linear layout)
// BM=128, BN=128, BK=16, 256 threads, 8x8 microtile, double-buffered smem.
// Epilogues: 0 = QKV scatter, 1 = +bias +residual, 2 = +bias +exact GELU
// ---------------------------------------------------------------------------
#define EPI_QKV      0
#define EPI_BIAS_RES 1
#define EPI_GELU     2

template<int EPI>
__global__ __launch_bounds__(256, 2) void gemm_kernel(
    const float* __restrict__ A, const float* __restrict__ W,
    const float* __restrict__ bias, const float* __restrict__ res,
    float* __restrict__ out, int Nn, int K)
{
    __shared__ float As[2][16][132];
    __shared__ float Ws[2][16][132];

    int tid = threadIdx.x;
    int tx = tid & 15, ty = tid >> 4;
    int m0 = blockIdx.y * 128, n0 = blockIdx.x * 128;
    int lr = tid >> 2, lc = tid & 3;

    const float* Aptr = A + (size_t)(m0 + lr) * K + lc * 4;
    const float* Wptr = W + (size_t)(n0 + lr) * K + lc * 4;

    float4 pa0 = *reinterpret_cast<const float4*>(Aptr);
    float4 pa1 = *reinterpret_cast<const float4*>(Aptr + (size_t)64 * K);
    float4 pw0 = *reinterpret_cast<const float4*>(Wptr);
    float4 pw1 = *reinterpret_cast<const float4*>(Wptr + (size_t)64 * K);

    // store tile 0 into buffer 0
    {
        As[0][lc*4+0][lr] = pa0.x; As[0][lc*4+1][lr] = pa0.y;
        As[0][lc*4+2][lr] = pa0.z; As[0][lc*4+3][lr] = pa0.w;
        As[0][lc*4+0][lr+64] = pa1.x; As[0][lc*4+1][lr+64] = pa1.y;
        As[0][lc*4+2][lr+64] = pa1.z; As[0][lc*4+3][lr+64] = pa1.w;
        Ws[0][lc*4+0][lr] = pw0.x; Ws[0][lc*4+1][lr] = pw0.y;
        Ws[0][lc*4+2][lr] = pw0.z; Ws[0][lc*4+3][lr] = pw0.w;
        Ws[0][lc*4+0][lr+64] = pw1.x; Ws[0][lc*4+1][lr+64] = pw1.y;
        Ws[0][lc*4+2][lr+64] = pw1.z; Ws[0][lc*4+3][lr+64] = pw1.w;
    }
    __syncthreads();

    float acc[8][8] = {};
    int nt = K >> 4;

    for (int t = 0; t < nt; t++) {
        int b = t & 1;
        if (t + 1 < nt) {
            const float* Ap = Aptr + (t + 1) * 16;
            const float* Wp = Wptr + (t + 1) * 16;
            pa0 = *reinterpret_cast<const float4*>(Ap);
            pa1 = *reinterpret_cast<const float4*>(Ap + (size_t)64 * K);
            pw0 = *reinterpret_cast<const float4*>(Wp);
            pw1 = *reinterpret_cast<const float4*>(Wp + (size_t)64 * K);
        }

        #pragma unroll
        for (int kk = 0; kk < 16; kk++) {
            float4 a0 = *reinterpret_cast<const float4*>(&As[b][kk][ty * 8]);
            float4 a1 = *reinterpret_cast<const float4*>(&As[b][kk][ty * 8 + 4]);
            float4 w0 = *reinterpret_cast<const float4*>(&Ws[b][kk][tx * 8]);
            float4 w1 = *reinterpret_cast<const float4*>(&Ws[b][kk][tx * 8 + 4]);
            float av[8] = {a0.x, a0.y, a0.z, a0.w, a1.x, a1.y, a1.z, a1.w};
            float wv[8] = {w0.x, w0.y, w0.z, w0.w, w1.x, w1.y, w1.z, w1.w};
            #pragma unroll
            for (int i = 0; i < 8; i++)
                #pragma unroll
                for (int j = 0; j < 8; j++)
                    acc[i][j] += av[i] * wv[j];
        }

        if (t + 1 < nt) {
            int nb = b ^ 1;
            As[nb][lc*4+0][lr] = pa0.x; As[nb][lc*4+1][lr] = pa0.y;
            As[nb][lc*4+2][lr] = pa0.z; As[nb][lc*4+3][lr] = pa0.w;
            As[nb][lc*4+0][lr+64] = pa1.x; As[nb][lc*4+1][lr+64] = pa1.y;
            As[nb][lc*4+2][lr+64] = pa1.z; As[nb][lc*4+3][lr+64] = pa1.w;
            Ws[nb][lc*4+0][lr] = pw0.x; Ws[nb][lc*4+1][lr] = pw0.y;
            Ws[nb][lc*4+2][lr] = pw0.z; Ws[nb][lc*4+3][lr] = pw0.w;
            Ws[nb][lc*4+0][lr+64] = pw1.x; Ws[nb][lc*4+1][lr+64] = pw1.y;
            Ws[nb][lc*4+2][lr+64] = pw1.z; Ws[nb][lc*4+3][lr+64] = pw1.w;
            __syncthreads();
        }
    }

    #pragma unroll
    for (int i = 0; i < 8; i++) {
        int m = m0 + ty * 8 + i;
        if (EPI == EPI_QKV) {
            int bb = m >> 11;
            int n  = m & 2047;
            #pragma unroll
            for (int u = 0; u < 8; u += 4) {
                int o = n0 + tx * 8 + u;
                int part = o >> 8;
                int rem  = o & 255;
                int h    = rem >> 5;
                int d    = rem & 31;
                float4 v = {acc[i][u], acc[i][u+1], acc[i][u+2], acc[i][u+3]};
                *reinterpret_cast<float4*>(
                    &out[(size_t)part * BHND +
                         ((size_t)(bb * H_NUM + h) * N_TOK + n) * D_HEAD + d]) = v;
            }
        } else if (EPI == EPI_BIAS_RES) {
            #pragma unroll
            for (int u = 0; u < 8; u += 4) {
                int o = n0 + tx * 8 + u;
                size_t idx = (size_t)m * Nn + o;
                float4 bv = *reinterpret_cast<const float4*>(&bias[o]);
                float4 rv = *reinterpret_cast<const float4*>(&res[idx]);
                float4 v = {acc[i][u]   + bv.x + rv.x,
                            acc[i][u+1] + bv.y + rv.y,
                            acc[i][u+2] + bv.z + rv.z,
                            acc[i][u+3] + bv.w + rv.w};
                *reinterpret_cast<float4*>(&out[idx]) = v;
            }
        } else { // GELU
            #pragma unroll
            for (int u = 0; u < 8; u += 4) {
                int o = n0 + tx * 8 + u;
                size_t idx = (size_t)m * Nn + o;
                float4 bv = *reinterpret_cast<const float4*>(&bias[o]);
                float vv[4] = {acc[i][u] + bv.x, acc[i][u+1] + bv.y,
                               acc[i][u+2] + bv.z, acc[i][u+3] + bv.w};
                float4 v;
                v.x = 0.5f * vv[0] * (1.0f + erff(vv[0] * 0.70710678f));
                v.y = 0.5f * vv[1] * (1.0f + erff(vv[1] * 0.70710678f));
                v.z = 0.5f * vv[2] * (1.0f + erff(vv[2] * 0.70710678f));
                v.w = 0.5f * vv[3] * (1.0f + erff(vv[3] * 0.70710678f));
                *reinterpret_cast<float4*>(&out[idx]) = v;
            }
        }
    }
}

// ---------------------------------------------------------------------------
// Attention: flash-style single pass (scores tiny -> exp without max shift).
// Grid (N/64, B*H), 128 threads. Q tile 64x32, KV tiles 64 rows.
// 8x4 microtile for QK^T (ty over 8 q-rows, tx over 4 kv-cols).
// Diagonal masked to exact zero probability.
// ---------------------------------------------------------------------------
__global__ __launch_bounds__(128) void attn_kernel(
    const float* __restrict__ Qg, const float* __restrict__ Kg,
    const float* __restrict__ Vg, const float* __restrict__ scale_p,
    float* __restrict__ Outg)
{
    __shared__ float Qs[32][68];  // d-major
    __shared__ float Ks[32][68];  // d-major
    __shared__ float Vs[64][34];  // row-major
    __shared__ float Ps[64][69];  // [q][kv], stride 69: conflict-free bcast reads

    int tid = threadIdx.x;
    int tx = tid & 15, ty = tid >> 4;   // ty 0..7
    int bh = blockIdx.y;
    int q0 = blockIdx.x * 64;
    const float scale = *scale_p;

    const float* Qb = Qg + (size_t)bh * N_TOK * D_HEAD;
    const float* Kb = Kg + (size_t)bh * N_TOK * D_HEAD;
    const float* Vb = Vg + (size_t)bh * N_TOK * D_HEAD;

    // Load Q tile (transposed to d-major): 4 float4 per thread
    #pragma unroll
    for (int r = 0; r < 4; r++) {
        int f = tid + r * 128;
        int row = f >> 3, seg = f & 7;
        float4 qv = *reinterpret_cast<const float4*>(Qb + (size_t)(q0 + row) * 32 + seg * 4);
        Qs[seg*4 + 0][row] = qv.x; Qs[seg*4 + 1][row] = qv.y;
        Qs[seg*4 + 2][row] = qv.z; Qs[seg*4 + 3][row] = qv.w;
    }

    float o_acc[8][2] = {};
    float l_acc[8]    = {};

    for (int t0 = 0; t0 < N_TOK; t0 += 64) {
        __syncthreads();  // previous iteration fully done with Ks/Vs/Ps
        #pragma unroll
        for (int r = 0; r < 4; r++) {
            int f = tid + r * 128;
            int row = f >> 3, seg = f & 7;
            float4 kv = *reinterpret_cast<const float4*>(Kb + (size_t)(t0 + row) * 32 + seg * 4);
            Ks[seg*4 + 0][row] = kv.x; Ks[seg*4 + 1][row] = kv.y;
            Ks[seg*4 + 2][row] = kv.z; Ks[seg*4 + 3][row] = kv.w;
            float4 vv = *reinterpret_cast<const float4*>(Vb + (size_t)(t0 + row) * 32 + seg * 4);
            Vs[row][seg*4 + 0] = vv.x; Vs[row][seg*4 + 1] = vv.y;
            Vs[row][seg*4 + 2] = vv.z; Vs[row][seg*4 + 3] = vv.w;
        }
        __syncthreads();

        // S = Q K^T : 8x4 per thread
        float s[8][4] = {};
        #pragma unroll
        for (int d = 0; d < 32; d++) {
            float4 a0 = *reinterpret_cast<const float4*>(&Qs[d][ty * 8]);
            float4 a1 = *reinterpret_cast<const float4*>(&Qs[d][ty * 8 + 4]);
            float4 k4 = *reinterpret_cast<const float4*>(&Ks[d][tx * 4]);
            float av[8] = {a0.x, a0.y, a0.z, a0.w, a1.x, a1.y, a1.z, a1.w};
            float kv[4] = {k4.x, k4.y, k4.z, k4.w};
            #pragma unroll
            for (int i = 0; i < 8; i++)
                #pragma unroll
                for (int j = 0; j < 4; j++)
                    s[i][j] += av[i] * kv[j];
        }

        // exp + diagonal mask + partial row sums
        #pragma unroll
        for (int i = 0; i < 8; i++) {
            int qi = q0 + ty * 8 + i;
            #pragma unroll
            for (int j = 0; j < 4; j++) {
                int kj = t0 + tx * 4 + j;
                float e = (qi == kj) ? 0.0f : __expf(s[i][j] * scale);
                Ps[ty*8 + i][tx*4 + j] = e;
                l_acc[i] += e;
            }
        }
        __syncthreads();

        // O += P V  (8 q-rows x 2 d-cols per thread)
        #pragma unroll 8
        for (int j = 0; j < 64; j++) {
            float2 v2 = *reinterpret_cast<const float2*>(&Vs[j][tx * 2]);
            #pragma unroll
            for (int i = 0; i < 8; i++) {
                float p = Ps[ty*8 + i][j];
                o_acc[i][0] += p * v2.x;
                o_acc[i][1] += p * v2.y;
            }
        }
    }

    // reduce l across the 16 tx lanes
    #pragma unroll
    for (int i = 0; i < 8; i++) {
        #pragma unroll
        for (int off = 1; off < 16; off <<= 1)
            l_acc[i] += __shfl_xor_sync(0xffffffffu, l_acc[i], off);
    }

    int bb = bh >> 3, h = bh & 7;
    #pragma unroll
    for (int i = 0; i < 8; i++) {
        float inv = 1.0f / l_acc[i];
        int n = q0 + ty * 8 + i;
        size_t base = ((size_t)(bb * N_TOK + n)) * C_DIM + h * D_HEAD + tx * 2;
        Outg[base]     = o_acc[i][0] * inv;
        Outg[base + 1] = o_acc[i][1] * inv;
    }
}

// ---------------------------------------------------------------------------
extern "C" void kernel_launch(void* const* d_in, const int* in_sizes, int n_in,
                              void* d_out, int out_size)
{
    const float* x      = (const float*)d_in[0];
    const float* ln1_g  = (const float*)d_in[1];
    const float* ln1_b  = (const float*)d_in[2];
    const float* qkv_w  = (const float*)d_in[3];
    const float* scale  = (const float*)d_in[4];
    const float* proj_w = (const float*)d_in[5];
    const float* proj_b = (const float*)d_in[6];
    const float* ln2_g  = (const float*)d_in[7];
    const float* ln2_b  = (const float*)d_in[8];
    const float* fc1_w  = (const float*)d_in[9];
    const float* fc1_b  = (const float*)d_in[10];
    const float* fc2_w  = (const float*)d_in[11];
    const float* fc2_b  = (const float*)d_in[12];
    float* out = (float*)d_out;

    float *p_xln, *p_qkv, *p_attn, *p_h;
    cudaGetSymbolAddress((void**)&p_xln,  g_xln);
    cudaGetSymbolAddress((void**)&p_qkv,  g_qkv);
    cudaGetSymbolAddress((void**)&p_attn, g_attn);
    cudaGetSymbolAddress((void**)&p_h,    g_h);

    dim3 lnBlock(32, 8);

    // 1. LN1
    ln_kernel<<<M_ROWS / 8, lnBlock>>>(x, ln1_g, ln1_b, p_xln);

    // 2. QKV projection with scatter to (3,B,H,N,D)
    gemm_kernel<EPI_QKV><<<dim3(768 / 128, M_ROWS / 128), 256>>>(
        p_xln, qkv_w, nullptr, nullptr, p_qkv, 768, C_DIM);

    // 3. Attention
    attn_kernel<<<dim3(N_TOK / 64, B_SZ * H_NUM), 128>>>(
        p_qkv, p_qkv + BHND, p_qkv + 2 * (size_t)BHND, scale, p_attn);

    // 4. proj + bias + residual -> out (= x after attention)
    gemm_kernel<EPI_BIAS_RES><<<dim3(C_DIM / 128, M_ROWS / 128), 256>>>(
        p_attn, proj_w, proj_b, x, out, C_DIM, C_DIM);

    // 5. LN2
    ln_kernel<<<M_ROWS / 8, lnBlock>>>(out, ln2_g, ln2_b, p_xln);

    // 6. fc1 + bias + exact GELU
    gemm_kernel<EPI_GELU><<<dim3(HID_D / 128, M_ROWS / 128), 256>>>(
        p_xln, fc1_w, fc1_b, nullptr, p_h, HID_D, C_DIM);

    // 7. fc2 + bias + residual -> out
    gemm_kernel<EPI_BIAS_RES><<<dim3(C_DIM / 128, M_ROWS / 128), 256>>>(
        p_h, fc2_w, fc2_b, out, out, C_DIM, HID_D);
}

// round 4
// speedup vs baseline: 1.2438x; 1.0099x over previous
#include <cuda_runtime.h>
#include <math.h>

#define B_SZ   8
#define N_TOK  2048
#define C_DIM  256
#define H_NUM  8
#define D_HEAD 32
#define HID_D  1024
#define M_ROWS (B_SZ * N_TOK)            /* 16384 */
#define BHND   (B_SZ * H_NUM * N_TOK * D_HEAD) /* 4194304 */

// Scratch (allocation-free: device globals)
__device__ float g_xln[(size_t)M_ROWS * C_DIM];
__device__ float g_qkv[(size_t)3 * BHND];
__device__ float g_attn[(size_t)M_ROWS * C_DIM];
__device__ float g_h[(size_t)M_ROWS * HID_D];

// ---------------------------------------------------------------------------
// Packed f32x2 helpers (FFMA2 path; ptxas never emits it from plain C++)
// ---------------------------------------------------------------------------
__device__ __forceinline__ unsigned long long pack2(float a) {
    unsigned long long r;
    asm("mov.b64 %0, {%1, %1};" : "=l"(r) : "f"(a));
    return r;
}
__device__ __forceinline__ void ffma2(unsigned long long& d,
                                      unsigned long long a,
                                      unsigned long long b) {
    asm("fma.rn.f32x2 %0, %1, %2, %0;" : "+l"(d) : "l"(a), "l"(b));
}
__device__ __forceinline__ float2 unpack2(unsigned long long v) {
    float2 f;
    asm("mov.b64 {%0, %1}, %2;" : "=f"(f.x), "=f"(f.y) : "l"(v));
    return f;
}

// ---------------------------------------------------------------------------
// LayerNorm: one warp per row of 256, blockDim (32, 8)
// ---------------------------------------------------------------------------
__global__ __launch_bounds__(256) void ln_kernel(
    const float* __restrict__ x, const float* __restrict__ g,
    const float* __restrict__ b, float* __restrict__ out)
{
    int row  = blockIdx.x * 8 + threadIdx.y;
    int lane = threadIdx.x;
    const float* xr = x + (size_t)row * C_DIM;

    float4 v0 = *reinterpret_cast<const float4*>(xr + lane * 4);
    float4 v1 = *reinterpret_cast<const float4*>(xr + 128 + lane * 4);

    float s  = v0.x + v0.y + v0.z + v0.w + v1.x + v1.y + v1.z + v1.w;
    float sq = v0.x*v0.x + v0.y*v0.y + v0.z*v0.z + v0.w*v0.w
             + v1.x*v1.x + v1.y*v1.y + v1.z*v1.z + v1.w*v1.w;

    #pragma unroll
    for (int off = 16; off > 0; off >>= 1) {
        s  += __shfl_xor_sync(0xffffffffu, s,  off);
        sq += __shfl_xor_sync(0xffffffffu, sq, off);
    }
    float mean = s * (1.0f / 256.0f);
    float var  = sq * (1.0f / 256.0f) - mean * mean;
    float rstd = rsqrtf(var + 1e-5f);

    float4 g0 = *reinterpret_cast<const float4*>(g + lane * 4);
    float4 g1 = *reinterpret_cast<const float4*>(g + 128 + lane * 4);
    float4 b0 = *reinterpret_cast<const float4*>(b + lane * 4);
    float4 b1 = *reinterpret_cast<const float4*>(b + 128 + lane * 4);

    float4 o0, o1;
    o0.x = (v0.x - mean) * rstd * g0.x + b0.x;
    o0.y = (v0.y - mean) * rstd * g0.y + b0.y;
    o0.z = (v0.z - mean) * rstd * g0.z + b0.z;
    o0.w = (v0.w - mean) * rstd * g0.w + b0.w;
    o1.x = (v1.x - mean) * rstd * g1.x + b1.x;
    o1.y = (v1.y - mean) * rstd * g1.y + b1.y;
    o1.z = (v1.z - mean) * rstd * g1.z + b1.z;
    o1.w = (v1.w - mean) * rstd * g1.w + b1.w;

    float* orow = out + (size_t)row * C_DIM;
    *reinterpret_cast<float4*>(orow + lane * 4)       = o0;
    *reinterpret_cast<float4*>(orow + 128 + lane * 4) = o1;
}

// ---------------------------------------------------------------------------
// GEMM: C[M,Nn] = A[M,K] @ W[Nn,K]^T  (torch Linear layout)
// BM=128, BN=128, BK=16, 256 threads, 8x8 microtile via f32x2 pairs,
// double-buffered smem.
// ---------------------------------------------------------------------------
#define EPI_QKV      0
#define EPI_BIAS_RES 1
#define EPI_GELU     2

template<int EPI>
__global__ __launch_bounds__(256, 2) void gemm_kernel(
    const float* __restrict__ A, const float* __restrict__ W,
    const float* __restrict__ bias, const float* __restrict__ res,
    float* __restrict__ out, int Nn, int K)
{
    __shared__ float As[2][16][132];
    __shared__ float Ws[2][16][132];

    int tid = threadIdx.x;
    int tx = tid & 15, ty = tid >> 4;
    int m0 = blockIdx.y * 128, n0 = blockIdx.x * 128;
    int lr = tid >> 2, lc = tid & 3;

    const float* Aptr = A + (size_t)(m0 + lr) * K + lc * 4;
    const float* Wptr = W + (size_t)(n0 + lr) * K + lc * 4;

    float4 pa0 = *reinterpret_cast<const float4*>(Aptr);
    float4 pa1 = *reinterpret_cast<const float4*>(Aptr + (size_t)64 * K);
    float4 pw0 = *reinterpret_cast<const float4*>(Wptr);
    float4 pw1 = *reinterpret_cast<const float4*>(Wptr + (size_t)64 * K);

    {
        As[0][lc*4+0][lr] = pa0.x; As[0][lc*4+1][lr] = pa0.y;
        As[0][lc*4+2][lr] = pa0.z; As[0][lc*4+3][lr] = pa0.w;
        As[0][lc*4+0][lr+64] = pa1.x; As[0][lc*4+1][lr+64] = pa1.y;
        As[0][lc*4+2][lr+64] = pa1.z; As[0][lc*4+3][lr+64] = pa1.w;
        Ws[0][lc*4+0][lr] = pw0.x; Ws[0][lc*4+1][lr] = pw0.y;
        Ws[0][lc*4+2][lr] = pw0.z; Ws[0][lc*4+3][lr] = pw0.w;
        Ws[0][lc*4+0][lr+64] = pw1.x; Ws[0][lc*4+1][lr+64] = pw1.y;
        Ws[0][lc*4+2][lr+64] = pw1.z; Ws[0][lc*4+3][lr+64] = pw1.w;
    }
    __syncthreads();

    unsigned long long acc[8][4] = {};   // bit pattern 0 == (0.f, 0.f)
    int nt = K >> 4;

    for (int t = 0; t < nt; t++) {
        int b = t & 1;
        if (t + 1 < nt) {
            const float* Ap = Aptr + (t + 1) * 16;
            const float* Wp = Wptr + (t + 1) * 16;
            pa0 = *reinterpret_cast<const float4*>(Ap);
            pa1 = *reinterpret_cast<const float4*>(Ap + (size_t)64 * K);
            pw0 = *reinterpret_cast<const float4*>(Wp);
            pw1 = *reinterpret_cast<const float4*>(Wp + (size_t)64 * K);
        }

        #pragma unroll
        for (int kk = 0; kk < 16; kk++) {
            float4 a0 = *reinterpret_cast<const float4*>(&As[b][kk][ty * 8]);
            float4 a1 = *reinterpret_cast<const float4*>(&As[b][kk][ty * 8 + 4]);
            ulonglong2 w0 = *reinterpret_cast<const ulonglong2*>(&Ws[b][kk][tx * 8]);
            ulonglong2 w1 = *reinterpret_cast<const ulonglong2*>(&Ws[b][kk][tx * 8 + 4]);
            float av[8] = {a0.x, a0.y, a0.z, a0.w, a1.x, a1.y, a1.z, a1.w};
            unsigned long long wp[4] = {w0.x, w0.y, w1.x, w1.y};
            #pragma unroll
            for (int i = 0; i < 8; i++) {
                unsigned long long ap = pack2(av[i]);
                ffma2(acc[i][0], ap, wp[0]);
                ffma2(acc[i][1], ap, wp[1]);
                ffma2(acc[i][2], ap, wp[2]);
                ffma2(acc[i][3], ap, wp[3]);
            }
        }

        if (t + 1 < nt) {
            int nb = b ^ 1;
            As[nb][lc*4+0][lr] = pa0.x; As[nb][lc*4+1][lr] = pa0.y;
            As[nb][lc*4+2][lr] = pa0.z; As[nb][lc*4+3][lr] = pa0.w;
            As[nb][lc*4+0][lr+64] = pa1.x; As[nb][lc*4+1][lr+64] = pa1.y;
            As[nb][lc*4+2][lr+64] = pa1.z; As[nb][lc*4+3][lr+64] = pa1.w;
            Ws[nb][lc*4+0][lr] = pw0.x; Ws[nb][lc*4+1][lr] = pw0.y;
            Ws[nb][lc*4+2][lr] = pw0.z; Ws[nb][lc*4+3][lr] = pw0.w;
            Ws[nb][lc*4+0][lr+64] = pw1.x; Ws[nb][lc*4+1][lr+64] = pw1.y;
            Ws[nb][lc*4+2][lr+64] = pw1.z; Ws[nb][lc*4+3][lr+64] = pw1.w;
            __syncthreads();
        }
    }

    #pragma unroll
    for (int i = 0; i < 8; i++) {
        int m = m0 + ty * 8 + i;
        float2 c0 = unpack2(acc[i][0]);
        float2 c1 = unpack2(acc[i][1]);
        float2 c2 = unpack2(acc[i][2]);
        float2 c3 = unpack2(acc[i][3]);
        float cc[8] = {c0.x, c0.y, c1.x, c1.y, c2.x, c2.y, c3.x, c3.y};

        if (EPI == EPI_QKV) {
            int bb = m >> 11;
            int n  = m & 2047;
            #pragma unroll
            for (int u = 0; u < 8; u += 4) {
                int o = n0 + tx * 8 + u;
                int part = o >> 8;
                int rem  = o & 255;
                int h    = rem >> 5;
                int d    = rem & 31;
                float4 v = {cc[u], cc[u+1], cc[u+2], cc[u+3]};
                *reinterpret_cast<float4*>(
                    &out[(size_t)part * BHND +
                         ((size_t)(bb * H_NUM + h) * N_TOK + n) * D_HEAD + d]) = v;
            }
        } else if (EPI == EPI_BIAS_RES) {
            #pragma unroll
            for (int u = 0; u < 8; u += 4) {
                int o = n0 + tx * 8 + u;
                size_t idx = (size_t)m * Nn + o;
                float4 bv = *reinterpret_cast<const float4*>(&bias[o]);
                float4 rv = *reinterpret_cast<const float4*>(&res[idx]);
                float4 v = {cc[u]   + bv.x + rv.x,
                            cc[u+1] + bv.y + rv.y,
                            cc[u+2] + bv.z + rv.z,
                            cc[u+3] + bv.w + rv.w};
                *reinterpret_cast<float4*>(&out[idx]) = v;
            }
        } else { // GELU
            #pragma unroll
            for (int u = 0; u < 8; u += 4) {
                int o = n0 + tx * 8 + u;
                size_t idx = (size_t)m * Nn + o;
                float4 bv = *reinterpret_cast<const float4*>(&bias[o]);
                float vv[4] = {cc[u] + bv.x, cc[u+1] + bv.y,
                               cc[u+2] + bv.z, cc[u+3] + bv.w};
                float4 v;
                v.x = 0.5f * vv[0] * (1.0f + erff(vv[0] * 0.70710678f));
                v.y = 0.5f * vv[1] * (1.0f + erff(vv[1] * 0.70710678f));
                v.z = 0.5f * vv[2] * (1.0f + erff(vv[2] * 0.70710678f));
                v.w = 0.5f * vv[3] * (1.0f + erff(vv[3] * 0.70710678f));
                *reinterpret_cast<float4*>(&out[idx]) = v;
            }
        }
    }
}

// ---------------------------------------------------------------------------
// Attention: flash-style single pass (scores tiny -> exp without max shift).
// Grid (N/64, B*H), 128 threads. Q tile 64x32, KV tiles 64 rows.
// QK^T: 8x4 microtile (pairs over kv cols). PV: pairs over j via Vjp layout.
// Diagonal masked to exact zero probability.
// ---------------------------------------------------------------------------
__global__ __launch_bounds__(128) void attn_kernel(
    const float* __restrict__ Qg, const float* __restrict__ Kg,
    const float* __restrict__ Vg, const float* __restrict__ scale_p,
    float* __restrict__ Outg)
{
    __shared__ float  Qs[32][68];   // d-major
    __shared__ float  Ks[32][68];   // d-major
    __shared__ float2 Vjp[32][34];  // Vjp[jp][d] = (V[2jp][d], V[2jp+1][d])
    __shared__ float  Ps[64][68];   // [q][kv]

    int tid = threadIdx.x;
    int tx = tid & 15, ty = tid >> 4;   // ty 0..7
    int bh = blockIdx.y;
    int q0 = blockIdx.x * 64;
    const float scale = *scale_p;

    const float* Qb = Qg + (size_t)bh * N_TOK * D_HEAD;
    const float* Kb = Kg + (size_t)bh * N_TOK * D_HEAD;
    const float* Vb = Vg + (size_t)bh * N_TOK * D_HEAD;

    // Load Q tile (transposed to d-major): 4 float4 per thread
    #pragma unroll
    for (int r = 0; r < 4; r++) {
        int f = tid + r * 128;
        int row = f >> 3, seg = f & 7;
        float4 qv = *reinterpret_cast<const float4*>(Qb + (size_t)(q0 + row) * 32 + seg * 4);
        Qs[seg*4 + 0][row] = qv.x; Qs[seg*4 + 1][row] = qv.y;
        Qs[seg*4 + 2][row] = qv.z; Qs[seg*4 + 3][row] = qv.w;
    }

    unsigned long long o2[8][2] = {};  // (even-j sum, odd-j sum) per (qrow, col)
    float l_acc[8] = {};

    for (int t0 = 0; t0 < N_TOK; t0 += 64) {
        __syncthreads();  // previous iteration done with Ks/Vjp/Ps
        #pragma unroll
        for (int r = 0; r < 4; r++) {
            int f = tid + r * 128;
            int row = f >> 3, seg = f & 7;
            float4 kv = *reinterpret_cast<const float4*>(Kb + (size_t)(t0 + row) * 32 + seg * 4);
            Ks[seg*4 + 0][row] = kv.x; Ks[seg*4 + 1][row] = kv.y;
            Ks[seg*4 + 2][row] = kv.z; Ks[seg*4 + 3][row] = kv.w;
            float4 vv = *reinterpret_cast<const float4*>(Vb + (size_t)(t0 + row) * 32 + seg * 4);
            int jp = row >> 1, par = row & 1;
            float* vbase = reinterpret_cast<float*>(&Vjp[jp][0]);
            vbase[(seg*4 + 0) * 2 + par] = vv.x;
            vbase[(seg*4 + 1) * 2 + par] = vv.y;
            vbase[(seg*4 + 2) * 2 + par] = vv.z;
            vbase[(seg*4 + 3) * 2 + par] = vv.w;
        }
        __syncthreads();

        // S = Q K^T : 8x4 per thread (pairs over kv index)
        unsigned long long s2[8][2] = {};
        #pragma unroll
        for (int d = 0; d < 32; d++) {
            float4 a0 = *reinterpret_cast<const float4*>(&Qs[d][ty * 8]);
            float4 a1 = *reinterpret_cast<const float4*>(&Qs[d][ty * 8 + 4]);
            ulonglong2 k2 = *reinterpret_cast<const ulonglong2*>(&Ks[d][tx * 4]);
            float av[8] = {a0.x, a0.y, a0.z, a0.w, a1.x, a1.y, a1.z, a1.w};
            #pragma unroll
            for (int i = 0; i < 8; i++) {
                unsigned long long ap = pack2(av[i]);
                ffma2(s2[i][0], ap, k2.x);
                ffma2(s2[i][1], ap, k2.y);
            }
        }

        // exp + diagonal mask + partial row sums
        #pragma unroll
        for (int i = 0; i < 8; i++) {
            int qi = q0 + ty * 8 + i;
            float2 sa = unpack2(s2[i][0]);
            float2 sb = unpack2(s2[i][1]);
            float sv[4] = {sa.x, sa.y, sb.x, sb.y};
            #pragma unroll
            for (int j = 0; j < 4; j++) {
                int kj = t0 + tx * 4 + j;
                float e = (qi == kj) ? 0.0f : __expf(sv[j] * scale);
                Ps[ty*8 + i][tx*4 + j] = e;
                l_acc[i] += e;
            }
        }
        __syncthreads();

        // O += P V : pairs over j. Per 4 j's: 10 LDS.128 + 32 FFMA2.
        #pragma unroll 4
        for (int jp = 0; jp < 32; jp += 2) {
            ulonglong2 va = *reinterpret_cast<const ulonglong2*>(&Vjp[jp][tx * 2]);
            ulonglong2 vb = *reinterpret_cast<const ulonglong2*>(&Vjp[jp + 1][tx * 2]);
            #pragma unroll
            for (int i = 0; i < 8; i++) {
                ulonglong2 pp = *reinterpret_cast<const ulonglong2*>(&Ps[ty*8 + i][jp * 2]);
                ffma2(o2[i][0], pp.x, va.x);
                ffma2(o2[i][1], pp.x, va.y);
                ffma2(o2[i][0], pp.y, vb.x);
                ffma2(o2[i][1], pp.y, vb.y);
            }
        }
    }

    // reduce l across the 16 tx lanes
    #pragma unroll
    for (int i = 0; i < 8; i++) {
        #pragma unroll
        for (int off = 1; off < 16; off <<= 1)
            l_acc[i] += __shfl_xor_sync(0xffffffffu, l_acc[i], off);
    }

    int bb = bh >> 3, h = bh & 7;
    #pragma unroll
    for (int i = 0; i < 8; i++) {
        float inv = 1.0f / l_acc[i];
        int n = q0 + ty * 8 + i;
        float2 oa = unpack2(o2[i][0]);
        float2 ob = unpack2(o2[i][1]);
        size_t base = ((size_t)(bb * N_TOK + n)) * C_DIM + h * D_HEAD + tx * 2;
        Outg[base]     = (oa.x + oa.y) * inv;
        Outg[base + 1] = (ob.x + ob.y) * inv;
    }
}

// ---------------------------------------------------------------------------
extern "C" void kernel_launch(void* const* d_in, const int* in_sizes, int n_in,
                              void* d_out, int out_size)
{
    const float* x      = (const float*)d_in[0];
    const float* ln1_g  = (const float*)d_in[1];
    const float* ln1_b  = (const float*)d_in[2];
    const float* qkv_w  = (const float*)d_in[3];
    const float* scale  = (const float*)d_in[4];
    const float* proj_w = (const float*)d_in[5];
    const float* proj_b = (const float*)d_in[6];
    const float* ln2_g  = (const float*)d_in[7];
    const float* ln2_b  = (const float*)d_in[8];
    const float* fc1_w  = (const float*)d_in[9];
    const float* fc1_b  = (const float*)d_in[10];
    const float* fc2_w  = (const float*)d_in[11];
    const float* fc2_b  = (const float*)d_in[12];
    float* out = (float*)d_out;

    float *p_xln, *p_qkv, *p_attn, *p_h;
    cudaGetSymbolAddress((void**)&p_xln,  g_xln);
    cudaGetSymbolAddress((void**)&p_qkv,  g_qkv);
    cudaGetSymbolAddress((void**)&p_attn, g_attn);
    cudaGetSymbolAddress((void**)&p_h,    g_h);

    dim3 lnBlock(32, 8);

    // 1. LN1
    ln_kernel<<<M_ROWS / 8, lnBlock>>>(x, ln1_g, ln1_b, p_xln);

    // 2. QKV projection with scatter to (3,B,H,N,D)
    gemm_kernel<EPI_QKV><<<dim3(768 / 128, M_ROWS / 128), 256>>>(
        p_xln, qkv_w, nullptr, nullptr, p_qkv, 768, C_DIM);

    // 3. Attention
    attn_kernel<<<dim3(N_TOK / 64, B_SZ * H_NUM), 128>>>(
        p_qkv, p_qkv + BHND, p_qkv + 2 * (size_t)BHND, scale, p_attn);

    // 4. proj + bias + residual -> out (= x after attention)
    gemm_kernel<EPI_BIAS_RES><<<dim3(C_DIM / 128, M_ROWS / 128), 256>>>(
        p_attn, proj_w, proj_b, x, out, C_DIM, C_DIM);

    // 5. LN2
    ln_kernel<<<M_ROWS / 8, lnBlock>>>(out, ln2_g, ln2_b, p_xln);

    // 6. fc1 + bias + exact GELU
    gemm_kernel<EPI_GELU><<<dim3(HID_D / 128, M_ROWS / 128), 256>>>(
        p_xln, fc1_w, fc1_b, nullptr, p_h, HID_D, C_DIM);

    // 7. fc2 + bias + residual -> out
    gemm_kernel<EPI_BIAS_RES><<<dim3(C_DIM / 128, M_ROWS / 128), 256>>>(
        p_h, fc2_w, fc2_b, out, out, C_DIM, HID_D);
}

// round 9
// speedup vs baseline: 3.1117x; 2.5018x over previous
#include <cuda_runtime.h>
#include <math.h>
#include <stdint.h>

#define B_SZ   8
#define N_TOK  2048
#define C_DIM  256
#define H_NUM  8
#define D_HEAD 32
#define HID_D  1024
#define M_ROWS (B_SZ * N_TOK)            /* 16384 */
#define BHND   (B_SZ * H_NUM * N_TOK * D_HEAD) /* 4194304 */

// Scratch (allocation-free: device globals)
__device__ float g_xln[(size_t)M_ROWS * C_DIM];
__device__ float g_qkv[(size_t)3 * BHND];
__device__ float g_attn[(size_t)M_ROWS * C_DIM];
__device__ float g_h[(size_t)M_ROWS * HID_D];

// ---------------------------------------------------------------------------
// Helpers
// ---------------------------------------------------------------------------
__device__ __forceinline__ uint32_t smem_u32(const void* p) {
    uint32_t a;
    asm("{ .reg .u64 t; cvta.to.shared.u64 t, %1; cvt.u32.u64 %0, t; }"
        : "=r"(a) : "l"(p));
    return a;
}
__device__ __forceinline__ void cp_async16(uint32_t dst, const void* src) {
    asm volatile("cp.async.cg.shared.global [%0], [%1], 16;" :: "r"(dst), "l"(src));
}
// m16n8k8 tf32 tensor-core mma (sm_80+; legal on plain sm_103 target)
__device__ __forceinline__ void mma_tf32(float* d, const uint32_t* a, const uint32_t* b) {
    asm volatile(
        "mma.sync.aligned.m16n8k8.row.col.f32.tf32.tf32.f32 "
        "{%0,%1,%2,%3}, {%4,%5,%6,%7}, {%8,%9}, {%0,%1,%2,%3};"
        : "+f"(d[0]), "+f"(d[1]), "+f"(d[2]), "+f"(d[3])
        : "r"(a[0]), "r"(a[1]), "r"(a[2]), "r"(a[3]), "r"(b[0]), "r"(b[1]));
}
__device__ __forceinline__ uint32_t ldsf(const float* p) {
    return __float_as_uint(*p);
}

// ---------------------------------------------------------------------------
// LayerNorm: one warp per row of 256, blockDim (32, 8)
// ---------------------------------------------------------------------------
__global__ __launch_bounds__(256) void ln_kernel(
    const float* __restrict__ x, const float* __restrict__ g,
    const float* __restrict__ b, float* __restrict__ out)
{
    int row  = blockIdx.x * 8 + threadIdx.y;
    int lane = threadIdx.x;
    const float* xr = x + (size_t)row * C_DIM;

    float4 v0 = *reinterpret_cast<const float4*>(xr + lane * 4);
    float4 v1 = *reinterpret_cast<const float4*>(xr + 128 + lane * 4);

    float s  = v0.x + v0.y + v0.z + v0.w + v1.x + v1.y + v1.z + v1.w;
    float sq = v0.x*v0.x + v0.y*v0.y + v0.z*v0.z + v0.w*v0.w
             + v1.x*v1.x + v1.y*v1.y + v1.z*v1.z + v1.w*v1.w;

    #pragma unroll
    for (int off = 16; off > 0; off >>= 1) {
        s  += __shfl_xor_sync(0xffffffffu, s,  off);
        sq += __shfl_xor_sync(0xffffffffu, sq, off);
    }
    float mean = s * (1.0f / 256.0f);
    float var  = sq * (1.0f / 256.0f) - mean * mean;
    float rstd = rsqrtf(var + 1e-5f);

    float4 g0 = *reinterpret_cast<const float4*>(g + lane * 4);
    float4 g1 = *reinterpret_cast<const float4*>(g + 128 + lane * 4);
    float4 b0 = *reinterpret_cast<const float4*>(b + lane * 4);
    float4 b1 = *reinterpret_cast<const float4*>(b + 128 + lane * 4);

    float4 o0, o1;
    o0.x = (v0.x - mean) * rstd * g0.x + b0.x;
    o0.y = (v0.y - mean) * rstd * g0.y + b0.y;
    o0.z = (v0.z - mean) * rstd * g0.z + b0.z;
    o0.w = (v0.w - mean) * rstd * g0.w + b0.w;
    o1.x = (v1.x - mean) * rstd * g1.x + b1.x;
    o1.y = (v1.y - mean) * rstd * g1.y + b1.y;
    o1.z = (v1.z - mean) * rstd * g1.z + b1.z;
    o1.w = (v1.w - mean) * rstd * g1.w + b1.w;

    float* orow = out + (size_t)row * C_DIM;
    *reinterpret_cast<float4*>(orow + lane * 4)       = o0;
    *reinterpret_cast<float4*>(orow + 128 + lane * 4) = o1;
}

// ---------------------------------------------------------------------------
// HMMA tf32 GEMM: C[M,Nn] = A[M,K] @ W[Nn,K]^T
// CTA 128x128, 256 thr, 8 warps (warp tile 64m x 32n), BK=32, cp.async 2-stage.
// smem: row-major, pad 36 words/row -> all fragment LDS are bank-conflict-free.
// ---------------------------------------------------------------------------
#define EPI_QKV      0
#define EPI_BIAS_RES 1
#define EPI_GELU     2

#define GSTAGE_W (128 * 36)                 /* words per tensor per stage */
#define GT_SMEM_BYTES (4 * GSTAGE_W * 4)    /* A0,W0,A1,W1 = 73728 B */

template<int EPI>
__global__ __launch_bounds__(256) void gemm_mma(
    const float* __restrict__ A, const float* __restrict__ W,
    const float* __restrict__ bias, const float* __restrict__ res,
    float* __restrict__ out, int Nn, int K)
{
    extern __shared__ float sm[];
    const int tid = threadIdx.x;
    const int wid = tid >> 5, lane = tid & 31;
    const int wm = wid >> 2, wn = wid & 3;       // warp grid 2 x 4
    const int r = lane >> 2, c = lane & 3;
    const int m0 = blockIdx.y * 128, n0 = blockIdx.x * 128;
    const uint32_t sb = smem_u32(sm);

    const int nst = K >> 5;

    // prologue: stage 0
    {
        #pragma unroll
        for (int i = 0; i < 4; i++) {
            int idx = tid + i * 256;
            int row = idx >> 3, seg = idx & 7;
            uint32_t so = (uint32_t)(row * 36 + seg * 4) * 4;
            cp_async16(sb + so, A + (size_t)(m0 + row) * K + seg * 4);
            cp_async16(sb + GSTAGE_W * 4 + so, W + (size_t)(n0 + row) * K + seg * 4);
        }
        asm volatile("cp.async.commit_group;" ::: "memory");
    }

    float acc[4][4][4];
    #pragma unroll
    for (int i = 0; i < 4; i++)
        #pragma unroll
        for (int j = 0; j < 4; j++)
            #pragma unroll
            for (int e = 0; e < 4; e++) acc[i][j][e] = 0.0f;

    for (int t = 0; t < nst; t++) {
        if (t + 1 < nst) {
            int kc = (t + 1) << 5;
            uint32_t base = sb + (uint32_t)((t + 1) & 1) * (2 * GSTAGE_W * 4);
            #pragma unroll
            for (int i = 0; i < 4; i++) {
                int idx = tid + i * 256;
                int row = idx >> 3, seg = idx & 7;
                uint32_t so = (uint32_t)(row * 36 + seg * 4) * 4;
                cp_async16(base + so, A + (size_t)(m0 + row) * K + kc + seg * 4);
                cp_async16(base + GSTAGE_W * 4 + so, W + (size_t)(n0 + row) * K + kc + seg * 4);
            }
            asm volatile("cp.async.commit_group;" ::: "memory");
            asm volatile("cp.async.wait_group 1;" ::: "memory");
        } else {
            asm volatile("cp.async.wait_group 0;" ::: "memory");
        }
        __syncthreads();   // stage t visible everywhere

        const float* As = sm + (t & 1) * (2 * GSTAGE_W);
        const float* Ws = As + GSTAGE_W;

        #pragma unroll
        for (int kk = 0; kk < 4; kk++) {
            int kb = kk * 8;
            uint32_t a[4][4], b[4][2];
            #pragma unroll
            for (int mt = 0; mt < 4; mt++) {
                const float* p = As + (wm * 64 + mt * 16 + r) * 36 + kb + c;
                a[mt][0] = ldsf(p);       a[mt][1] = ldsf(p + 288);
                a[mt][2] = ldsf(p + 4);   a[mt][3] = ldsf(p + 292);
            }
            #pragma unroll
            for (int nt = 0; nt < 4; nt++) {
                const float* p = Ws + (wn * 32 + nt * 8 + r) * 36 + kb + c;
                b[nt][0] = ldsf(p);       b[nt][1] = ldsf(p + 4);
            }
            #pragma unroll
            for (int mt = 0; mt < 4; mt++)
                #pragma unroll
                for (int nt = 0; nt < 4; nt++)
                    mma_tf32(acc[mt][nt], a[mt], b[nt]);
        }
        __syncthreads();   // all done with stage t (its buffer reused at t+2)
    }

    // epilogue: per (mt,nt): rows R0, R0+8, cols Cc, Cc+1 (float2)
    #pragma unroll
    for (int mt = 0; mt < 4; mt++) {
        int R0 = m0 + wm * 64 + mt * 16 + r;
        #pragma unroll
        for (int nt = 0; nt < 4; nt++) {
            int Cc = n0 + wn * 32 + nt * 8 + 2 * c;
            float2 v01 = {acc[mt][nt][0], acc[mt][nt][1]};
            float2 v23 = {acc[mt][nt][2], acc[mt][nt][3]};

            if (EPI == EPI_QKV) {
                int part = Cc >> 8, h = (Cc & 255) >> 5, d = Cc & 31;
                int bb0 = R0 >> 11, n_0 = R0 & 2047;
                int R1 = R0 + 8;
                int bb1 = R1 >> 11, n_1 = R1 & 2047;
                (void)out;
                *reinterpret_cast<float2*>(
                    &g_qkv[(size_t)part * BHND +
                           ((size_t)(bb0 * H_NUM + h) * N_TOK + n_0) * D_HEAD + d]) = v01;
                *reinterpret_cast<float2*>(
                    &g_qkv[(size_t)part * BHND +
                           ((size_t)(bb1 * H_NUM + h) * N_TOK + n_1) * D_HEAD + d]) = v23;
            } else if (EPI == EPI_BIAS_RES) {
                float2 b2 = *reinterpret_cast<const float2*>(&bias[Cc]);
                size_t i0 = (size_t)R0 * Nn + Cc;
                size_t i1 = (size_t)(R0 + 8) * Nn + Cc;
                float2 r0 = *reinterpret_cast<const float2*>(&res[i0]);
                float2 r1 = *reinterpret_cast<const float2*>(&res[i1]);
                float2 o0 = {v01.x + b2.x + r0.x, v01.y + b2.y + r0.y};
                float2 o1 = {v23.x + b2.x + r1.x, v23.y + b2.y + r1.y};
                *reinterpret_cast<float2*>(&out[i0]) = o0;
                *reinterpret_cast<float2*>(&out[i1]) = o1;
            } else { // GELU
                float2 b2 = *reinterpret_cast<const float2*>(&bias[Cc]);
                size_t i0 = (size_t)R0 * Nn + Cc;
                size_t i1 = (size_t)(R0 + 8) * Nn + Cc;
                float u0 = v01.x + b2.x, u1 = v01.y + b2.y;
                float u2 = v23.x + b2.x, u3 = v23.y + b2.y;
                float2 o0 = {0.5f * u0 * (1.0f + erff(u0 * 0.70710678f)),
                             0.5f * u1 * (1.0f + erff(u1 * 0.70710678f))};
                float2 o1 = {0.5f * u2 * (1.0f + erff(u2 * 0.70710678f)),
                             0.5f * u3 * (1.0f + erff(u3 * 0.70710678f))};
                *reinterpret_cast<float2*>(&out[i0]) = o0;
                *reinterpret_cast<float2*>(&out[i1]) = o1;
            }
        }
    }
}

// ---------------------------------------------------------------------------
// Attention (HMMA tf32): grid (N/64, B*H), 128 threads = 4 warps.
// Warp w owns q-rows [q0+16w, q0+16w+16). Per 64-token KV tile:
//   S = Q K^T via mma (8 n-tiles x 4 k-tiles), exp on fragments (diag->0),
//   P staged through per-warp smem rows (intra-warp relayout, __syncwarp),
//   O += P V via mma (4 d-tiles x 8 k-tiles). Single-pass (no max shift).
// Ps stride 68: 64 kv columns + pad (fragment reads bank-conflict-free).
// ---------------------------------------------------------------------------
__global__ __launch_bounds__(128) void attn_mma(
    const float* __restrict__ Qg, const float* __restrict__ Kg,
    const float* __restrict__ Vg, const float* __restrict__ scale_p,
    float* __restrict__ Outg)
{
    __shared__ float Qs[64][36];
    __shared__ float Ks[64][36];
    __shared__ float Vs[64][40];   // pad 40: B-frag reads (8k+n) bank-unique
    __shared__ float Ps[64][68];   // [q][kv 0..63], pad 4

    const int tid = threadIdx.x;
    const int w = tid >> 5, lane = tid & 31;
    const int r = lane >> 2, c = lane & 3;
    const int bh = blockIdx.y;
    const int q0 = blockIdx.x * 64;
    const float scale = *scale_p;

    const float* Qb = Qg + (size_t)bh * N_TOK * D_HEAD;
    const float* Kb = Kg + (size_t)bh * N_TOK * D_HEAD;
    const float* Vb = Vg + (size_t)bh * N_TOK * D_HEAD;

    // load Q tile
    #pragma unroll
    for (int i = 0; i < 4; i++) {
        int idx = tid + i * 128;
        int row = idx >> 3, seg = idx & 7;
        float4 q4 = *reinterpret_cast<const float4*>(Qb + (size_t)(q0 + row) * 32 + seg * 4);
        *reinterpret_cast<float4*>(&Qs[row][seg * 4]) = q4;
    }
    __syncthreads();

    // hoist Q fragments (fixed all loop): 4 k-tiles x 4 regs
    uint32_t qa[4][4];
    #pragma unroll
    for (int kt = 0; kt < 4; kt++) {
        const float* p = &Qs[w * 16 + r][kt * 8 + c];
        qa[kt][0] = ldsf(p);       qa[kt][1] = ldsf(p + 288);
        qa[kt][2] = ldsf(p + 4);   qa[kt][3] = ldsf(p + 292);
    }

    float oacc[4][4];
    #pragma unroll
    for (int i = 0; i < 4; i++)
        #pragma unroll
        for (int e = 0; e < 4; e++) oacc[i][e] = 0.0f;
    float l0 = 0.0f, l1 = 0.0f;

    for (int t0 = 0; t0 < N_TOK; t0 += 64) {
        __syncthreads();   // previous tile's PV reads of Ks/Vs complete
        #pragma unroll
        for (int i = 0; i < 4; i++) {
            int idx = tid + i * 128;
            int row = idx >> 3, seg = idx & 7;
            float4 k4 = *reinterpret_cast<const float4*>(Kb + (size_t)(t0 + row) * 32 + seg * 4);
            *reinterpret_cast<float4*>(&Ks[row][seg * 4]) = k4;
            float4 v4 = *reinterpret_cast<const float4*>(Vb + (size_t)(t0 + row) * 32 + seg * 4);
            *reinterpret_cast<float4*>(&Vs[row][seg * 4]) = v4;
        }
        __syncthreads();

        // S = Q K^T : 8 n-tiles (64 kv) x 4 k-tiles (d=32)
        float sacc[8][4];
        #pragma unroll
        for (int nt = 0; nt < 8; nt++) {
            #pragma unroll
            for (int e = 0; e < 4; e++) sacc[nt][e] = 0.0f;
            uint32_t kb4[4][2];
            #pragma unroll
            for (int kt = 0; kt < 4; kt++) {
                const float* p = &Ks[nt * 8 + r][kt * 8 + c];
                kb4[kt][0] = ldsf(p); kb4[kt][1] = ldsf(p + 4);
            }
            #pragma unroll
            for (int kt = 0; kt < 4; kt++)
                mma_tf32(sacc[nt], qa[kt], kb4[kt]);
        }

        // exp + diagonal mask + l partials; store P (per-warp rows)
        int qi0 = q0 + w * 16 + r;
        #pragma unroll
        for (int nt = 0; nt < 8; nt++) {
            int kj = t0 + nt * 8 + 2 * c;
            float e0 = (qi0     == kj    ) ? 0.0f : __expf(sacc[nt][0] * scale);
            float e1 = (qi0     == kj + 1) ? 0.0f : __expf(sacc[nt][1] * scale);
            float e2 = (qi0 + 8 == kj    ) ? 0.0f : __expf(sacc[nt][2] * scale);
            float e3 = (qi0 + 8 == kj + 1) ? 0.0f : __expf(sacc[nt][3] * scale);
            l0 += e0 + e1;
            l1 += e2 + e3;
            *reinterpret_cast<float2*>(&Ps[w * 16 + r    ][nt * 8 + 2 * c]) = make_float2(e0, e1);
            *reinterpret_cast<float2*>(&Ps[w * 16 + r + 8][nt * 8 + 2 * c]) = make_float2(e2, e3);
        }
        __syncwarp();

        // O += P V : 8 k-tiles (kv) x 4 n-tiles (d=32). Ps stride 68.
        #pragma unroll
        for (int kt = 0; kt < 8; kt++) {
            uint32_t pa[4];
            {
                const float* p = &Ps[w * 16 + r][kt * 8 + c];
                pa[0] = ldsf(p);       pa[1] = ldsf(p + 544);
                pa[2] = ldsf(p + 4);   pa[3] = ldsf(p + 548);
            }
            #pragma unroll
            for (int nt = 0; nt < 4; nt++) {
                uint32_t vb[2];
                const float* p = &Vs[kt * 8 + c][nt * 8 + r];
                vb[0] = ldsf(p); vb[1] = ldsf(p + 160);   // k+4 rows -> +4*40
                mma_tf32(oacc[nt], pa, vb);
            }
        }
        __syncwarp();   // Ps reads done before next tile overwrites (same warp)
    }

    // reduce l over the 4 lanes of each row group
    #pragma unroll
    for (int off = 1; off < 4; off <<= 1) {
        l0 += __shfl_xor_sync(0xffffffffu, l0, off);
        l1 += __shfl_xor_sync(0xffffffffu, l1, off);
    }
    float inv0 = 1.0f / l0, inv1 = 1.0f / l1;

    int bb = bh >> 3, h = bh & 7;
    int n_0 = q0 + w * 16 + r;
    #pragma unroll
    for (int nt = 0; nt < 4; nt++) {
        int d = nt * 8 + 2 * c;
        size_t base0 = ((size_t)(bb * N_TOK + n_0)) * C_DIM + h * D_HEAD + d;
        size_t base1 = ((size_t)(bb * N_TOK + n_0 + 8)) * C_DIM + h * D_HEAD + d;
        *reinterpret_cast<float2*>(&Outg[base0]) =
            make_float2(oacc[nt][0] * inv0, oacc[nt][1] * inv0);
        *reinterpret_cast<float2*>(&Outg[base1]) =
            make_float2(oacc[nt][2] * inv1, oacc[nt][3] * inv1);
    }
}

// ---------------------------------------------------------------------------
extern "C" void kernel_launch(void* const* d_in, const int* in_sizes, int n_in,
                              void* d_out, int out_size)
{
    const float* x      = (const float*)d_in[0];
    const float* ln1_g  = (const float*)d_in[1];
    const float* ln1_b  = (const float*)d_in[2];
    const float* qkv_w  = (const float*)d_in[3];
    const float* scale  = (const float*)d_in[4];
    const float* proj_w = (const float*)d_in[5];
    const float* proj_b = (const float*)d_in[6];
    const float* ln2_g  = (const float*)d_in[7];
    const float* ln2_b  = (const float*)d_in[8];
    const float* fc1_w  = (const float*)d_in[9];
    const float* fc1_b  = (const float*)d_in[10];
    const float* fc2_w  = (const float*)d_in[11];
    const float* fc2_b  = (const float*)d_in[12];
    float* out = (float*)d_out;

    float *p_xln, *p_qkv, *p_attn, *p_h;
    cudaGetSymbolAddress((void**)&p_xln,  g_xln);
    cudaGetSymbolAddress((void**)&p_qkv,  g_qkv);
    cudaGetSymbolAddress((void**)&p_attn, g_attn);
    cudaGetSymbolAddress((void**)&p_h,    g_h);

    cudaFuncSetAttribute(gemm_mma<EPI_QKV>,
        cudaFuncAttributeMaxDynamicSharedMemorySize, GT_SMEM_BYTES);
    cudaFuncSetAttribute(gemm_mma<EPI_BIAS_RES>,
        cudaFuncAttributeMaxDynamicSharedMemorySize, GT_SMEM_BYTES);
    cudaFuncSetAttribute(gemm_mma<EPI_GELU>,
        cudaFuncAttributeMaxDynamicSharedMemorySize, GT_SMEM_BYTES);

    dim3 lnBlock(32, 8);

    // 1. LN1
    ln_kernel<<<M_ROWS / 8, lnBlock>>>(x, ln1_g, ln1_b, p_xln);

    // 2. QKV projection (HMMA tf32) with scatter to (3,B,H,N,D)
    gemm_mma<EPI_QKV><<<dim3(768 / 128, M_ROWS / 128), 256, GT_SMEM_BYTES>>>(
        p_xln, qkv_w, nullptr, nullptr, p_qkv, 768, C_DIM);

    // 3. Attention (HMMA tf32)
    attn_mma<<<dim3(N_TOK / 64, B_SZ * H_NUM), 128>>>(
        p_qkv, p_qkv + BHND, p_qkv + 2 * (size_t)BHND, scale, p_attn);

    // 4. proj + bias + residual -> out
    gemm_mma<EPI_BIAS_RES><<<dim3(C_DIM / 128, M_ROWS / 128), 256, GT_SMEM_BYTES>>>(
        p_attn, proj_w, proj_b, x, out, C_DIM, C_DIM);

    // 5. LN2
    ln_kernel<<<M_ROWS / 8, lnBlock>>>(out, ln2_g, ln2_b, p_xln);

    // 6. fc1 + bias + exact GELU
    gemm_mma<EPI_GELU><<<dim3(HID_D / 128, M_ROWS / 128), 256, GT_SMEM_BYTES>>>(
        p_xln, fc1_w, fc1_b, nullptr, p_h, HID_D, C_DIM);

    // 7. fc2 + bias + residual -> out
    gemm_mma<EPI_BIAS_RES><<<dim3(C_DIM / 128, M_ROWS / 128), 256, GT_SMEM_BYTES>>>(
        p_h, fc2_w, fc2_b, out, out, C_DIM, HID_D);
}

// round 11
// speedup vs baseline: 3.2886x; 1.0568x over previous
#include <cuda_runtime.h>
#include <math.h>
#include <stdint.h>

#define B_SZ   8
#define N_TOK  2048
#define C_DIM  256
#define H_NUM  8
#define D_HEAD 32
#define HID_D  1024
#define M_ROWS (B_SZ * N_TOK)            /* 16384 */
#define BHND   (B_SZ * H_NUM * N_TOK * D_HEAD) /* 4194304 */

// Scratch (allocation-free: device globals)
__device__ float g_xln[(size_t)M_ROWS * C_DIM];
__device__ float g_qkv[(size_t)3 * BHND];
__device__ float g_attn[(size_t)M_ROWS * C_DIM];
__device__ float g_h[(size_t)M_ROWS * HID_D];

// ---------------------------------------------------------------------------
// Helpers
// ---------------------------------------------------------------------------
__device__ __forceinline__ uint32_t smem_u32(const void* p) {
    uint32_t a;
    asm("{ .reg .u64 t; cvta.to.shared.u64 t, %1; cvt.u32.u64 %0, t; }"
        : "=r"(a) : "l"(p));
    return a;
}
__device__ __forceinline__ void cp_async16(uint32_t dst, const void* src) {
    asm volatile("cp.async.cg.shared.global [%0], [%1], 16;" :: "r"(dst), "l"(src));
}
// m16n8k8 tf32 tensor-core mma (sm_80+; legal on plain sm_103 target)
__device__ __forceinline__ void mma_tf32(float* d, const uint32_t* a, const uint32_t* b) {
    asm volatile(
        "mma.sync.aligned.m16n8k8.row.col.f32.tf32.tf32.f32 "
        "{%0,%1,%2,%3}, {%4,%5,%6,%7}, {%8,%9}, {%0,%1,%2,%3};"
        : "+f"(d[0]), "+f"(d[1]), "+f"(d[2]), "+f"(d[3])
        : "r"(a[0]), "r"(a[1]), "r"(a[2]), "r"(a[3]), "r"(b[0]), "r"(b[1]));
}
__device__ __forceinline__ uint32_t ldsf(const float* p) {
    return __float_as_uint(*p);
}

// ---------------------------------------------------------------------------
// LayerNorm: one warp per row of 256, blockDim (32, 8)
// ---------------------------------------------------------------------------
__global__ __launch_bounds__(256) void ln_kernel(
    const float* __restrict__ x, const float* __restrict__ g,
    const float* __restrict__ b, float* __restrict__ out)
{
    int row  = blockIdx.x * 8 + threadIdx.y;
    int lane = threadIdx.x;
    const float* xr = x + (size_t)row * C_DIM;

    float4 v0 = *reinterpret_cast<const float4*>(xr + lane * 4);
    float4 v1 = *reinterpret_cast<const float4*>(xr + 128 + lane * 4);

    float s  = v0.x + v0.y + v0.z + v0.w + v1.x + v1.y + v1.z + v1.w;
    float sq = v0.x*v0.x + v0.y*v0.y + v0.z*v0.z + v0.w*v0.w
             + v1.x*v1.x + v1.y*v1.y + v1.z*v1.z + v1.w*v1.w;

    #pragma unroll
    for (int off = 16; off > 0; off >>= 1) {
        s  += __shfl_xor_sync(0xffffffffu, s,  off);
        sq += __shfl_xor_sync(0xffffffffu, sq, off);
    }
    float mean = s * (1.0f / 256.0f);
    float var  = sq * (1.0f / 256.0f) - mean * mean;
    float rstd = rsqrtf(var + 1e-5f);

    float4 g0 = *reinterpret_cast<const float4*>(g + lane * 4);
    float4 g1 = *reinterpret_cast<const float4*>(g + 128 + lane * 4);
    float4 b0 = *reinterpret_cast<const float4*>(b + lane * 4);
    float4 b1 = *reinterpret_cast<const float4*>(b + 128 + lane * 4);

    float4 o0, o1;
    o0.x = (v0.x - mean) * rstd * g0.x + b0.x;
    o0.y = (v0.y - mean) * rstd * g0.y + b0.y;
    o0.z = (v0.z - mean) * rstd * g0.z + b0.z;
    o0.w = (v0.w - mean) * rstd * g0.w + b0.w;
    o1.x = (v1.x - mean) * rstd * g1.x + b1.x;
    o1.y = (v1.y - mean) * rstd * g1.y + b1.y;
    o1.z = (v1.z - mean) * rstd * g1.z + b1.z;
    o1.w = (v1.w - mean) * rstd * g1.w + b1.w;

    float* orow = out + (size_t)row * C_DIM;
    *reinterpret_cast<float4*>(orow + lane * 4)       = o0;
    *reinterpret_cast<float4*>(orow + 128 + lane * 4) = o1;
}

// ---------------------------------------------------------------------------
// HMMA tf32 GEMM: C[M,Nn] = A[M,K] @ W[Nn,K]^T
// CTA 128x128, 256 thr, 8 warps (warp tile 64m x 32n), BK=32, cp.async 2-stage.
// __launch_bounds__(256,2): cap 128 regs -> 2 CTAs/SM (RF was the occupancy
// limiter at 130 regs: 1 CTA, occ 12%).
// ---------------------------------------------------------------------------
#define EPI_QKV      0
#define EPI_BIAS_RES 1
#define EPI_GELU     2

#define GSTAGE_W (128 * 36)                 /* words per tensor per stage */
#define GT_SMEM_BYTES (4 * GSTAGE_W * 4)    /* A0,W0,A1,W1 = 73728 B */

template<int EPI>
__global__ __launch_bounds__(256, 2) void gemm_mma(
    const float* __restrict__ A, const float* __restrict__ W,
    const float* __restrict__ bias, const float* __restrict__ res,
    float* __restrict__ out, int Nn, int K)
{
    extern __shared__ float sm[];
    const int tid = threadIdx.x;
    const int wid = tid >> 5, lane = tid & 31;
    const int wm = wid >> 2, wn = wid & 3;       // warp grid 2 x 4
    const int r = lane >> 2, c = lane & 3;
    const int m0 = blockIdx.y * 128, n0 = blockIdx.x * 128;
    const uint32_t sb = smem_u32(sm);

    const int nst = K >> 5;

    // prologue: stage 0
    {
        #pragma unroll
        for (int i = 0; i < 4; i++) {
            int idx = tid + i * 256;
            int row = idx >> 3, seg = idx & 7;
            uint32_t so = (uint32_t)(row * 36 + seg * 4) * 4;
            cp_async16(sb + so, A + (size_t)(m0 + row) * K + seg * 4);
            cp_async16(sb + GSTAGE_W * 4 + so, W + (size_t)(n0 + row) * K + seg * 4);
        }
        asm volatile("cp.async.commit_group;" ::: "memory");
    }

    float acc[4][4][4];
    #pragma unroll
    for (int i = 0; i < 4; i++)
        #pragma unroll
        for (int j = 0; j < 4; j++)
            #pragma unroll
            for (int e = 0; e < 4; e++) acc[i][j][e] = 0.0f;

    for (int t = 0; t < nst; t++) {
        if (t + 1 < nst) {
            int kc = (t + 1) << 5;
            uint32_t base = sb + (uint32_t)((t + 1) & 1) * (2 * GSTAGE_W * 4);
            #pragma unroll
            for (int i = 0; i < 4; i++) {
                int idx = tid + i * 256;
                int row = idx >> 3, seg = idx & 7;
                uint32_t so = (uint32_t)(row * 36 + seg * 4) * 4;
                cp_async16(base + so, A + (size_t)(m0 + row) * K + kc + seg * 4);
                cp_async16(base + GSTAGE_W * 4 + so, W + (size_t)(n0 + row) * K + kc + seg * 4);
            }
            asm volatile("cp.async.commit_group;" ::: "memory");
            asm volatile("cp.async.wait_group 1;" ::: "memory");
        } else {
            asm volatile("cp.async.wait_group 0;" ::: "memory");
        }
        __syncthreads();   // stage t visible everywhere

        const float* As = sm + (t & 1) * (2 * GSTAGE_W);
        const float* Ws = As + GSTAGE_W;

        #pragma unroll
        for (int kk = 0; kk < 4; kk++) {
            int kb = kk * 8;
            uint32_t a[4][4], b[4][2];
            #pragma unroll
            for (int mt = 0; mt < 4; mt++) {
                const float* p = As + (wm * 64 + mt * 16 + r) * 36 + kb + c;
                a[mt][0] = ldsf(p);       a[mt][1] = ldsf(p + 288);
                a[mt][2] = ldsf(p + 4);   a[mt][3] = ldsf(p + 292);
            }
            #pragma unroll
            for (int nt = 0; nt < 4; nt++) {
                const float* p = Ws + (wn * 32 + nt * 8 + r) * 36 + kb + c;
                b[nt][0] = ldsf(p);       b[nt][1] = ldsf(p + 4);
            }
            #pragma unroll
            for (int mt = 0; mt < 4; mt++)
                #pragma unroll
                for (int nt = 0; nt < 4; nt++)
                    mma_tf32(acc[mt][nt], a[mt], b[nt]);
        }
        __syncthreads();   // all done with stage t (its buffer reused at t+2)
    }

    // epilogue: per (mt,nt): rows R0, R0+8, cols Cc, Cc+1 (float2)
    #pragma unroll
    for (int mt = 0; mt < 4; mt++) {
        int R0 = m0 + wm * 64 + mt * 16 + r;
        #pragma unroll
        for (int nt = 0; nt < 4; nt++) {
            int Cc = n0 + wn * 32 + nt * 8 + 2 * c;
            float2 v01 = {acc[mt][nt][0], acc[mt][nt][1]};
            float2 v23 = {acc[mt][nt][2], acc[mt][nt][3]};

            if (EPI == EPI_QKV) {
                int part = Cc >> 8, h = (Cc & 255) >> 5, d = Cc & 31;
                int bb0 = R0 >> 11, n_0 = R0 & 2047;
                int R1 = R0 + 8;
                int bb1 = R1 >> 11, n_1 = R1 & 2047;
                (void)out;
                *reinterpret_cast<float2*>(
                    &g_qkv[(size_t)part * BHND +
                           ((size_t)(bb0 * H_NUM + h) * N_TOK + n_0) * D_HEAD + d]) = v01;
                *reinterpret_cast<float2*>(
                    &g_qkv[(size_t)part * BHND +
                           ((size_t)(bb1 * H_NUM + h) * N_TOK + n_1) * D_HEAD + d]) = v23;
            } else if (EPI == EPI_BIAS_RES) {
                float2 b2 = *reinterpret_cast<const float2*>(&bias[Cc]);
                size_t i0 = (size_t)R0 * Nn + Cc;
                size_t i1 = (size_t)(R0 + 8) * Nn + Cc;
                float2 r0 = *reinterpret_cast<const float2*>(&res[i0]);
                float2 r1 = *reinterpret_cast<const float2*>(&res[i1]);
                float2 o0 = {v01.x + b2.x + r0.x, v01.y + b2.y + r0.y};
                float2 o1 = {v23.x + b2.x + r1.x, v23.y + b2.y + r1.y};
                *reinterpret_cast<float2*>(&out[i0]) = o0;
                *reinterpret_cast<float2*>(&out[i1]) = o1;
            } else { // GELU
                float2 b2 = *reinterpret_cast<const float2*>(&bias[Cc]);
                size_t i0 = (size_t)R0 * Nn + Cc;
                size_t i1 = (size_t)(R0 + 8) * Nn + Cc;
                float u0 = v01.x + b2.x, u1 = v01.y + b2.y;
                float u2 = v23.x + b2.x, u3 = v23.y + b2.y;
                float2 o0 = {0.5f * u0 * (1.0f + erff(u0 * 0.70710678f)),
                             0.5f * u1 * (1.0f + erff(u1 * 0.70710678f))};
                float2 o1 = {0.5f * u2 * (1.0f + erff(u2 * 0.70710678f)),
                             0.5f * u3 * (1.0f + erff(u3 * 0.70710678f))};
                *reinterpret_cast<float2*>(&out[i0]) = o0;
                *reinterpret_cast<float2*>(&out[i1]) = o1;
            }
        }
    }
}

// ---------------------------------------------------------------------------
// Attention (HMMA tf32): grid (N/128, B*H), 256 threads = 8 warps.
// Q tile 128 rows per CTA (warp w owns rows [128*bx + 16w, +16)) -> halves
// K/V global traffic vs the 64-row version and doubles mma per KV load.
// Dynamic smem layout (words): Qs[128][36] | Ks[64][36] | Vs[64][40] | Ps[128][68]
// ---------------------------------------------------------------------------
#define AT_QS  0
#define AT_KS  (128 * 36)
#define AT_VS  (AT_KS + 64 * 36)
#define AT_PS  (AT_VS + 64 * 40)
#define AT_SMEM_WORDS (AT_PS + 128 * 68)
#define AT_SMEM_BYTES (AT_SMEM_WORDS * 4)   /* 72704 B */

__global__ __launch_bounds__(256) void attn_mma(
    const float* __restrict__ Qg, const float* __restrict__ Kg,
    const float* __restrict__ Vg, const float* __restrict__ scale_p,
    float* __restrict__ Outg)
{
    extern __shared__ float asm_[];
    float* Qs = asm_ + AT_QS;   // stride 36
    float* Ks = asm_ + AT_KS;   // stride 36
    float* Vs = asm_ + AT_VS;   // stride 40
    float* Ps = asm_ + AT_PS;   // stride 68

    const int tid = threadIdx.x;
    const int w = tid >> 5, lane = tid & 31;
    const int r = lane >> 2, c = lane & 3;
    const int bh = blockIdx.y;
    const int q0 = blockIdx.x * 128;
    const float scale = *scale_p;

    const float* Qb = Qg + (size_t)bh * N_TOK * D_HEAD;
    const float* Kb = Kg + (size_t)bh * N_TOK * D_HEAD;
    const float* Vb = Vg + (size_t)bh * N_TOK * D_HEAD;

    // load Q tile: 128 rows x 32 = 1024 float4, 256 thr x 4
    #pragma unroll
    for (int i = 0; i < 4; i++) {
        int idx = tid + i * 256;
        int row = idx >> 3, seg = idx & 7;
        float4 q4 = *reinterpret_cast<const float4*>(Qb + (size_t)(q0 + row) * 32 + seg * 4);
        *reinterpret_cast<float4*>(&Qs[row * 36 + seg * 4]) = q4;
    }
    __syncthreads();

    // hoist Q fragments: 4 k-tiles x 4 regs (rows w*16 + r / + 8)
    uint32_t qa[4][4];
    #pragma unroll
    for (int kt = 0; kt < 4; kt++) {
        const float* p = &Qs[(w * 16 + r) * 36 + kt * 8 + c];
        qa[kt][0] = ldsf(p);       qa[kt][1] = ldsf(p + 288);
        qa[kt][2] = ldsf(p + 4);   qa[kt][3] = ldsf(p + 292);
    }

    float oacc[4][4];
    #pragma unroll
    for (int i = 0; i < 4; i++)
        #pragma unroll
        for (int e = 0; e < 4; e++) oacc[i][e] = 0.0f;
    float l0 = 0.0f, l1 = 0.0f;

    for (int t0 = 0; t0 < N_TOK; t0 += 64) {
        __syncthreads();   // previous tile's PV reads of Ks/Vs complete
        // load K/V tile: 64 rows x 32 = 512 float4 each, 256 thr x 2
        #pragma unroll
        for (int i = 0; i < 2; i++) {
            int idx = tid + i * 256;
            int row = idx >> 3, seg = idx & 7;
            float4 k4 = *reinterpret_cast<const float4*>(Kb + (size_t)(t0 + row) * 32 + seg * 4);
            *reinterpret_cast<float4*>(&Ks[row * 36 + seg * 4]) = k4;
            float4 v4 = *reinterpret_cast<const float4*>(Vb + (size_t)(t0 + row) * 32 + seg * 4);
            *reinterpret_cast<float4*>(&Vs[row * 40 + seg * 4]) = v4;
        }
        __syncthreads();

        // S = Q K^T : 8 n-tiles (64 kv) x 4 k-tiles (d=32)
        float sacc[8][4];
        #pragma unroll
        for (int nt = 0; nt < 8; nt++) {
            #pragma unroll
            for (int e = 0; e < 4; e++) sacc[nt][e] = 0.0f;
            uint32_t kb4[4][2];
            #pragma unroll
            for (int kt = 0; kt < 4; kt++) {
                const float* p = &Ks[(nt * 8 + r) * 36 + kt * 8 + c];
                kb4[kt][0] = ldsf(p); kb4[kt][1] = ldsf(p + 4);
            }
            #pragma unroll
            for (int kt = 0; kt < 4; kt++)
                mma_tf32(sacc[nt], qa[kt], kb4[kt]);
        }

        // exp + diagonal mask + l partials; store P (per-warp rows)
        int qi0 = q0 + w * 16 + r;
        #pragma unroll
        for (int nt = 0; nt < 8; nt++) {
            int kj = t0 + nt * 8 + 2 * c;
            float e0 = (qi0     == kj    ) ? 0.0f : __expf(sacc[nt][0] * scale);
            float e1 = (qi0     == kj + 1) ? 0.0f : __expf(sacc[nt][1] * scale);
            float e2 = (qi0 + 8 == kj    ) ? 0.0f : __expf(sacc[nt][2] * scale);
            float e3 = (qi0 + 8 == kj + 1) ? 0.0f : __expf(sacc[nt][3] * scale);
            l0 += e0 + e1;
            l1 += e2 + e3;
            *reinterpret_cast<float2*>(&Ps[(w * 16 + r    ) * 68 + nt * 8 + 2 * c]) = make_float2(e0, e1);
            *reinterpret_cast<float2*>(&Ps[(w * 16 + r + 8) * 68 + nt * 8 + 2 * c]) = make_float2(e2, e3);
        }
        __syncwarp();

        // O += P V : 8 k-tiles (kv) x 4 n-tiles (d=32). Ps stride 68.
        #pragma unroll
        for (int kt = 0; kt < 8; kt++) {
            uint32_t pa[4];
            {
                const float* p = &Ps[(w * 16 + r) * 68 + kt * 8 + c];
                pa[0] = ldsf(p);       pa[1] = ldsf(p + 544);
                pa[2] = ldsf(p + 4);   pa[3] = ldsf(p + 548);
            }
            #pragma unroll
            for (int nt = 0; nt < 4; nt++) {
                uint32_t vb[2];
                const float* p = &Vs[(kt * 8 + c) * 40 + nt * 8 + r];
                vb[0] = ldsf(p); vb[1] = ldsf(p + 160);   // k+4 rows -> +4*40
                mma_tf32(oacc[nt], pa, vb);
            }
        }
        __syncwarp();   // Ps reads done before next tile overwrites (same warp)
    }

    // reduce l over the 4 lanes of each row group
    #pragma unroll
    for (int off = 1; off < 4; off <<= 1) {
        l0 += __shfl_xor_sync(0xffffffffu, l0, off);
        l1 += __shfl_xor_sync(0xffffffffu, l1, off);
    }
    float inv0 = 1.0f / l0, inv1 = 1.0f / l1;

    int bb = bh >> 3, h = bh & 7;
    int n_0 = q0 + w * 16 + r;
    #pragma unroll
    for (int nt = 0; nt < 4; nt++) {
        int d = nt * 8 + 2 * c;
        size_t base0 = ((size_t)(bb * N_TOK + n_0)) * C_DIM + h * D_HEAD + d;
        size_t base1 = ((size_t)(bb * N_TOK + n_0 + 8)) * C_DIM + h * D_HEAD + d;
        *reinterpret_cast<float2*>(&Outg[base0]) =
            make_float2(oacc[nt][0] * inv0, oacc[nt][1] * inv0);
        *reinterpret_cast<float2*>(&Outg[base1]) =
            make_float2(oacc[nt][2] * inv1, oacc[nt][3] * inv1);
    }
}

// ---------------------------------------------------------------------------
extern "C" void kernel_launch(void* const* d_in, const int* in_sizes, int n_in,
                              void* d_out, int out_size)
{
    const float* x      = (const float*)d_in[0];
    const float* ln1_g  = (const float*)d_in[1];
    const float* ln1_b  = (const float*)d_in[2];
    const float* qkv_w  = (const float*)d_in[3];
    const float* scale  = (const float*)d_in[4];
    const float* proj_w = (const float*)d_in[5];
    const float* proj_b = (const float*)d_in[6];
    const float* ln2_g  = (const float*)d_in[7];
    const float* ln2_b  = (const float*)d_in[8];
    const float* fc1_w  = (const float*)d_in[9];
    const float* fc1_b  = (const float*)d_in[10];
    const float* fc2_w  = (const float*)d_in[11];
    const float* fc2_b  = (const float*)d_in[12];
    float* out = (float*)d_out;

    float *p_xln, *p_qkv, *p_attn, *p_h;
    cudaGetSymbolAddress((void**)&p_xln,  g_xln);
    cudaGetSymbolAddress((void**)&p_qkv,  g_qkv);
    cudaGetSymbolAddress((void**)&p_attn, g_attn);
    cudaGetSymbolAddress((void**)&p_h,    g_h);

    cudaFuncSetAttribute(gemm_mma<EPI_QKV>,
        cudaFuncAttributeMaxDynamicSharedMemorySize, GT_SMEM_BYTES);
    cudaFuncSetAttribute(gemm_mma<EPI_BIAS_RES>,
        cudaFuncAttributeMaxDynamicSharedMemorySize, GT_SMEM_BYTES);
    cudaFuncSetAttribute(gemm_mma<EPI_GELU>,
        cudaFuncAttributeMaxDynamicSharedMemorySize, GT_SMEM_BYTES);
    cudaFuncSetAttribute(attn_mma,
        cudaFuncAttributeMaxDynamicSharedMemorySize, AT_SMEM_BYTES);

    dim3 lnBlock(32, 8);

    // 1. LN1
    ln_kernel<<<M_ROWS / 8, lnBlock>>>(x, ln1_g, ln1_b, p_xln);

    // 2. QKV projection (HMMA tf32) with scatter to (3,B,H,N,D)
    gemm_mma<EPI_QKV><<<dim3(768 / 128, M_ROWS / 128), 256, GT_SMEM_BYTES>>>(
        p_xln, qkv_w, nullptr, nullptr, p_qkv, 768, C_DIM);

    // 3. Attention (HMMA tf32), 128-row Q tiles
    attn_mma<<<dim3(N_TOK / 128, B_SZ * H_NUM), 256, AT_SMEM_BYTES>>>(
        p_qkv, p_qkv + BHND, p_qkv + 2 * (size_t)BHND, scale, p_attn);

    // 4. proj + bias + residual -> out
    gemm_mma<EPI_BIAS_RES><<<dim3(C_DIM / 128, M_ROWS / 128), 256, GT_SMEM_BYTES>>>(
        p_attn, proj_w, proj_b, x, out, C_DIM, C_DIM);

    // 5. LN2
    ln_kernel<<<M_ROWS / 8, lnBlock>>>(out, ln2_g, ln2_b, p_xln);

    // 6. fc1 + bias + exact GELU
    gemm_mma<EPI_GELU><<<dim3(HID_D / 128, M_ROWS / 128), 256, GT_SMEM_BYTES>>>(
        p_xln, fc1_w, fc1_b, nullptr, p_h, HID_D, C_DIM);

    // 7. fc2 + bias + residual -> out
    gemm_mma<EPI_BIAS_RES><<<dim3(C_DIM / 128, M_ROWS / 128), 256, GT_SMEM_BYTES>>>(
        p_h, fc2_w, fc2_b, out, out, C_DIM, HID_D);
}

// round 13
// speedup vs baseline: 3.7119x; 1.1287x over previous
#include <cuda_runtime.h>
#include <math.h>
#include <stdint.h>

#define B_SZ   8
#define N_TOK  2048
#define C_DIM  256
#define H_NUM  8
#define D_HEAD 32
#define HID_D  1024
#define M_ROWS (B_SZ * N_TOK)            /* 16384 */
#define BHND   (B_SZ * H_NUM * N_TOK * D_HEAD) /* 4194304 */

// Scratch (allocation-free: device globals)
__device__ float g_xln[(size_t)M_ROWS * C_DIM];
__device__ float g_qkv[(size_t)3 * BHND];
__device__ float g_attn[(size_t)M_ROWS * C_DIM];
__device__ float g_h[(size_t)M_ROWS * HID_D];

// ---------------------------------------------------------------------------
// Helpers
// ---------------------------------------------------------------------------
__device__ __forceinline__ uint32_t smem_u32(const void* p) {
    uint32_t a;
    asm("{ .reg .u64 t; cvta.to.shared.u64 t, %1; cvt.u32.u64 %0, t; }"
        : "=r"(a) : "l"(p));
    return a;
}
__device__ __forceinline__ void cp_async16(uint32_t dst, const void* src) {
    asm volatile("cp.async.cg.shared.global [%0], [%1], 16;" :: "r"(dst), "l"(src));
}
// m16n8k8 tf32 tensor-core mma (sm_80+; legal on plain sm_103 target)
__device__ __forceinline__ void mma_tf32(float* d, const uint32_t* a, const uint32_t* b) {
    asm volatile(
        "mma.sync.aligned.m16n8k8.row.col.f32.tf32.tf32.f32 "
        "{%0,%1,%2,%3}, {%4,%5,%6,%7}, {%8,%9}, {%0,%1,%2,%3};"
        : "+f"(d[0]), "+f"(d[1]), "+f"(d[2]), "+f"(d[3])
        : "r"(a[0]), "r"(a[1]), "r"(a[2]), "r"(a[3]), "r"(b[0]), "r"(b[1]));
}
__device__ __forceinline__ uint32_t ldsf(const float* p) {
    return __float_as_uint(*p);
}
__device__ __forceinline__ float ex2f(float x) {
    float r;
    asm("ex2.approx.ftz.f32 %0, %1;" : "=f"(r) : "f"(x));
    return r;
}

// ---------------------------------------------------------------------------
// LayerNorm: one warp per row of 256, blockDim (32, 8)
// ---------------------------------------------------------------------------
__global__ __launch_bounds__(256) void ln_kernel(
    const float* __restrict__ x, const float* __restrict__ g,
    const float* __restrict__ b, float* __restrict__ out)
{
    int row  = blockIdx.x * 8 + threadIdx.y;
    int lane = threadIdx.x;
    const float* xr = x + (size_t)row * C_DIM;

    float4 v0 = *reinterpret_cast<const float4*>(xr + lane * 4);
    float4 v1 = *reinterpret_cast<const float4*>(xr + 128 + lane * 4);

    float s  = v0.x + v0.y + v0.z + v0.w + v1.x + v1.y + v1.z + v1.w;
    float sq = v0.x*v0.x + v0.y*v0.y + v0.z*v0.z + v0.w*v0.w
             + v1.x*v1.x + v1.y*v1.y + v1.z*v1.z + v1.w*v1.w;

    #pragma unroll
    for (int off = 16; off > 0; off >>= 1) {
        s  += __shfl_xor_sync(0xffffffffu, s,  off);
        sq += __shfl_xor_sync(0xffffffffu, sq, off);
    }
    float mean = s * (1.0f / 256.0f);
    float var  = sq * (1.0f / 256.0f) - mean * mean;
    float rstd = rsqrtf(var + 1e-5f);

    float4 g0 = *reinterpret_cast<const float4*>(g + lane * 4);
    float4 g1 = *reinterpret_cast<const float4*>(g + 128 + lane * 4);
    float4 b0 = *reinterpret_cast<const float4*>(b + lane * 4);
    float4 b1 = *reinterpret_cast<const float4*>(b + 128 + lane * 4);

    float4 o0, o1;
    o0.x = (v0.x - mean) * rstd * g0.x + b0.x;
    o0.y = (v0.y - mean) * rstd * g0.y + b0.y;
    o0.z = (v0.z - mean) * rstd * g0.z + b0.z;
    o0.w = (v0.w - mean) * rstd * g0.w + b0.w;
    o1.x = (v1.x - mean) * rstd * g1.x + b1.x;
    o1.y = (v1.y - mean) * rstd * g1.y + b1.y;
    o1.z = (v1.z - mean) * rstd * g1.z + b1.z;
    o1.w = (v1.w - mean) * rstd * g1.w + b1.w;

    float* orow = out + (size_t)row * C_DIM;
    *reinterpret_cast<float4*>(orow + lane * 4)       = o0;
    *reinterpret_cast<float4*>(orow + 128 + lane * 4) = o1;
}

// ---------------------------------------------------------------------------
// HMMA tf32 GEMM: C[M,Nn] = A[M,K] @ W[Nn,K]^T
// CTA 128x128, 256 thr, 8 warps (64m x 32n), BK=32, cp.async 2-stage,
// SINGLE __syncthreads per k-tile:
//   wait_group 0 (stage t in) -> sync (also orders compute t-1 before the
//   stores into buffer (t+1)&1, which was last read at t-1) -> issue t+1
//   -> compute t.
// ---------------------------------------------------------------------------
#define EPI_QKV      0
#define EPI_BIAS_RES 1
#define EPI_GELU     2

#define GSTAGE_W (128 * 36)                 /* words per tensor per stage */
#define GT_SMEM_BYTES (4 * GSTAGE_W * 4)    /* A0,W0,A1,W1 = 73728 B */

template<int EPI>
__global__ __launch_bounds__(256, 2) void gemm_mma(
    const float* __restrict__ A, const float* __restrict__ W,
    const float* __restrict__ bias, const float* __restrict__ res,
    float* __restrict__ out, int Nn, int K)
{
    extern __shared__ float sm[];
    const int tid = threadIdx.x;
    const int wid = tid >> 5, lane = tid & 31;
    const int wm = wid >> 2, wn = wid & 3;       // warp grid 2 x 4
    const int r = lane >> 2, c = lane & 3;
    const int m0 = blockIdx.y * 128, n0 = blockIdx.x * 128;
    const uint32_t sb = smem_u32(sm);

    const int nst = K >> 5;
    const int ldrow = tid >> 3, ldseg = tid & 7;
    const uint32_t ldoff = (uint32_t)(ldrow * 36 + ldseg * 4) * 4;
    const float* Arow0 = A + (size_t)(m0 + ldrow) * K + ldseg * 4;
    const float* Wrow0 = W + (size_t)(n0 + ldrow) * K + ldseg * 4;

    // prologue: stage 0 (each thread: 4 rows apart by 32)
    #pragma unroll
    for (int i = 0; i < 4; i++) {
        uint32_t so = ldoff + (uint32_t)(i * 32 * 36) * 4;
        cp_async16(sb + so, Arow0 + (size_t)(i * 32) * K);
        cp_async16(sb + GSTAGE_W * 4 + so, Wrow0 + (size_t)(i * 32) * K);
    }
    asm volatile("cp.async.commit_group;" ::: "memory");

    float acc[4][4][4];
    #pragma unroll
    for (int i = 0; i < 4; i++)
        #pragma unroll
        for (int j = 0; j < 4; j++)
            #pragma unroll
            for (int e = 0; e < 4; e++) acc[i][j][e] = 0.0f;

    for (int t = 0; t < nst; t++) {
        asm volatile("cp.async.wait_group 0;" ::: "memory");
        __syncthreads();   // stage t visible; compute t-1 done by all warps

        if (t + 1 < nst) {
            int kc = (t + 1) << 5;
            uint32_t base = sb + (uint32_t)((t + 1) & 1) * (2 * GSTAGE_W * 4);
            #pragma unroll
            for (int i = 0; i < 4; i++) {
                uint32_t so = ldoff + (uint32_t)(i * 32 * 36) * 4;
                cp_async16(base + so, Arow0 + (size_t)(i * 32) * K + kc);
                cp_async16(base + GSTAGE_W * 4 + so, Wrow0 + (size_t)(i * 32) * K + kc);
            }
            asm volatile("cp.async.commit_group;" ::: "memory");
        }

        const float* As = sm + (t & 1) * (2 * GSTAGE_W);
        const float* Ws = As + GSTAGE_W;

        #pragma unroll
        for (int kk = 0; kk < 4; kk++) {
            int kb = kk * 8;
            uint32_t a[4][4], b[4][2];
            #pragma unroll
            for (int mt = 0; mt < 4; mt++) {
                const float* p = As + (wm * 64 + mt * 16 + r) * 36 + kb + c;
                a[mt][0] = ldsf(p);       a[mt][1] = ldsf(p + 288);
                a[mt][2] = ldsf(p + 4);   a[mt][3] = ldsf(p + 292);
            }
            #pragma unroll
            for (int nt = 0; nt < 4; nt++) {
                const float* p = Ws + (wn * 32 + nt * 8 + r) * 36 + kb + c;
                b[nt][0] = ldsf(p);       b[nt][1] = ldsf(p + 4);
            }
            #pragma unroll
            for (int mt = 0; mt < 4; mt++)
                #pragma unroll
                for (int nt = 0; nt < 4; nt++)
                    mma_tf32(acc[mt][nt], a[mt], b[nt]);
        }
    }

    // epilogue: per (mt,nt): rows R0, R0+8, cols Cc, Cc+1 (float2)
    #pragma unroll
    for (int mt = 0; mt < 4; mt++) {
        int R0 = m0 + wm * 64 + mt * 16 + r;
        #pragma unroll
        for (int nt = 0; nt < 4; nt++) {
            int Cc = n0 + wn * 32 + nt * 8 + 2 * c;
            float2 v01 = {acc[mt][nt][0], acc[mt][nt][1]};
            float2 v23 = {acc[mt][nt][2], acc[mt][nt][3]};

            if (EPI == EPI_QKV) {
                int part = Cc >> 8, h = (Cc & 255) >> 5, d = Cc & 31;
                int bb0 = R0 >> 11, n_0 = R0 & 2047;
                int R1 = R0 + 8;
                int bb1 = R1 >> 11, n_1 = R1 & 2047;
                (void)out;
                *reinterpret_cast<float2*>(
                    &g_qkv[(size_t)part * BHND +
                           ((size_t)(bb0 * H_NUM + h) * N_TOK + n_0) * D_HEAD + d]) = v01;
                *reinterpret_cast<float2*>(
                    &g_qkv[(size_t)part * BHND +
                           ((size_t)(bb1 * H_NUM + h) * N_TOK + n_1) * D_HEAD + d]) = v23;
            } else if (EPI == EPI_BIAS_RES) {
                float2 b2 = *reinterpret_cast<const float2*>(&bias[Cc]);
                size_t i0 = (size_t)R0 * Nn + Cc;
                size_t i1 = (size_t)(R0 + 8) * Nn + Cc;
                float2 r0 = *reinterpret_cast<const float2*>(&res[i0]);
                float2 r1 = *reinterpret_cast<const float2*>(&res[i1]);
                float2 o0 = {v01.x + b2.x + r0.x, v01.y + b2.y + r0.y};
                float2 o1 = {v23.x + b2.x + r1.x, v23.y + b2.y + r1.y};
                *reinterpret_cast<float2*>(&out[i0]) = o0;
                *reinterpret_cast<float2*>(&out[i1]) = o1;
            } else { // GELU
                float2 b2 = *reinterpret_cast<const float2*>(&bias[Cc]);
                size_t i0 = (size_t)R0 * Nn + Cc;
                size_t i1 = (size_t)(R0 + 8) * Nn + Cc;
                float u0 = v01.x + b2.x, u1 = v01.y + b2.y;
                float u2 = v23.x + b2.x, u3 = v23.y + b2.y;
                float2 o0 = {0.5f * u0 * (1.0f + erff(u0 * 0.70710678f)),
                             0.5f * u1 * (1.0f + erff(u1 * 0.70710678f))};
                float2 o1 = {0.5f * u2 * (1.0f + erff(u2 * 0.70710678f)),
                             0.5f * u3 * (1.0f + erff(u3 * 0.70710678f))};
                *reinterpret_cast<float2*>(&out[i0]) = o0;
                *reinterpret_cast<float2*>(&out[i1]) = o1;
            }
        }
    }
}

// ---------------------------------------------------------------------------
// Attention (HMMA tf32): grid (N/128, B*H), 256 threads = 8 warps.
// Q tile 128 rows; KV tiles 64 rows, cp.async DOUBLE-BUFFERED with a single
// __syncthreads per tile (same pipeline proof as the GEMM).
// exp via ex2.approx with log2e folded into scale.
// smem (words): Qs[128][36] | Ks[2][64][36] | Vs[2][64][40] | Ps[128][68]
// ---------------------------------------------------------------------------
#define AT_QS  0
#define AT_KS  (128 * 36)                      /* 2 stages of 64*36 */
#define AT_VS  (AT_KS + 2 * 64 * 36)
#define AT_PS  (AT_VS + 2 * 64 * 40)
#define AT_SMEM_WORDS (AT_PS + 128 * 68)
#define AT_SMEM_BYTES (AT_SMEM_WORDS * 4)      /* 92160 B */

__global__ __launch_bounds__(256) void attn_mma(
    const float* __restrict__ Qg, const float* __restrict__ Kg,
    const float* __restrict__ Vg, const float* __restrict__ scale_p,
    float* __restrict__ Outg)
{
    extern __shared__ float asm_[];
    float* Qs = asm_ + AT_QS;   // stride 36
    float* Ps = asm_ + AT_PS;   // stride 68

    const int tid = threadIdx.x;
    const int w = tid >> 5, lane = tid & 31;
    const int r = lane >> 2, c = lane & 3;
    const int bh = blockIdx.y;
    const int q0 = blockIdx.x * 128;
    const float scale2 = (*scale_p) * 1.4426950408889634f;  // * log2(e)

    const float* Qb = Qg + (size_t)bh * N_TOK * D_HEAD;
    const float* Kb = Kg + (size_t)bh * N_TOK * D_HEAD;
    const float* Vb = Vg + (size_t)bh * N_TOK * D_HEAD;

    const uint32_t sb = smem_u32(asm_);
    const int ldrow = tid >> 3, ldseg = tid & 7;   // 32 rows x 8 segs per pass

    // prologue: issue KV tile 0 into stage 0
    {
        #pragma unroll
        for (int i = 0; i < 2; i++) {
            int row = ldrow + i * 32;
            cp_async16(sb + (AT_KS + row * 36 + ldseg * 4) * 4,
                       Kb + (size_t)row * 32 + ldseg * 4);
            cp_async16(sb + (AT_VS + row * 40 + ldseg * 4) * 4,
                       Vb + (size_t)row * 32 + ldseg * 4);
        }
        asm volatile("cp.async.commit_group;" ::: "memory");
    }

    // load Q tile (plain): 128 rows x 32
    #pragma unroll
    for (int i = 0; i < 4; i++) {
        int idx = tid + i * 256;
        int row = idx >> 3, seg = idx & 7;
        float4 q4 = *reinterpret_cast<const float4*>(Qb + (size_t)(q0 + row) * 32 + seg * 4);
        *reinterpret_cast<float4*>(&Qs[row * 36 + seg * 4]) = q4;
    }
    __syncthreads();

    // hoist Q fragments: 4 k-tiles x 4 regs
    uint32_t qa[4][4];
    #pragma unroll
    for (int kt = 0; kt < 4; kt++) {
        const float* p = &Qs[(w * 16 + r) * 36 + kt * 8 + c];
        qa[kt][0] = ldsf(p);       qa[kt][1] = ldsf(p + 288);
        qa[kt][2] = ldsf(p + 4);   qa[kt][3] = ldsf(p + 292);
    }

    float oacc[4][4];
    #pragma unroll
    for (int i = 0; i < 4; i++)
        #pragma unroll
        for (int e = 0; e < 4; e++) oacc[i][e] = 0.0f;
    float l0 = 0.0f, l1 = 0.0f;

    const int ntiles = N_TOK / 64;
    for (int tt = 0; tt < ntiles; tt++) {
        asm volatile("cp.async.wait_group 0;" ::: "memory");
        __syncthreads();   // KV stage tt visible; compute tt-1 done by all

        if (tt + 1 < ntiles) {
            int t1 = (tt + 1) * 64;
            uint32_t kbase = AT_KS + ((tt + 1) & 1) * (64 * 36);
            uint32_t vbase = AT_VS + ((tt + 1) & 1) * (64 * 40);
            #pragma unroll
            for (int i = 0; i < 2; i++) {
                int row = ldrow + i * 32;
                cp_async16(sb + (kbase + row * 36 + ldseg * 4) * 4,
                           Kb + (size_t)(t1 + row) * 32 + ldseg * 4);
                cp_async16(sb + (vbase + row * 40 + ldseg * 4) * 4,
                           Vb + (size_t)(t1 + row) * 32 + ldseg * 4);
            }
            asm volatile("cp.async.commit_group;" ::: "memory");
        }

        const float* Ks = asm_ + AT_KS + (tt & 1) * (64 * 36);
        const float* Vs = asm_ + AT_VS + (tt & 1) * (64 * 40);
        const int t0 = tt * 64;

        // S = Q K^T : 8 n-tiles (64 kv) x 4 k-tiles (d=32)
        float sacc[8][4];
        #pragma unroll
        for (int nt = 0; nt < 8; nt++) {
            #pragma unroll
            for (int e = 0; e < 4; e++) sacc[nt][e] = 0.0f;
            uint32_t kb4[4][2];
            #pragma unroll
            for (int kt = 0; kt < 4; kt++) {
                const float* p = &Ks[(nt * 8 + r) * 36 + kt * 8 + c];
                kb4[kt][0] = ldsf(p); kb4[kt][1] = ldsf(p + 4);
            }
            #pragma unroll
            for (int kt = 0; kt < 4; kt++)
                mma_tf32(sacc[nt], qa[kt], kb4[kt]);
        }

        // exp (ex2) + diagonal mask + l partials; store P (per-warp rows)
        int qi0 = q0 + w * 16 + r;
        #pragma unroll
        for (int nt = 0; nt < 8; nt++) {
            int kj = t0 + nt * 8 + 2 * c;
            float e0 = (qi0     == kj    ) ? 0.0f : ex2f(sacc[nt][0] * scale2);
            float e1 = (qi0     == kj + 1) ? 0.0f : ex2f(sacc[nt][1] * scale2);
            float e2 = (qi0 + 8 == kj    ) ? 0.0f : ex2f(sacc[nt][2] * scale2);
            float e3 = (qi0 + 8 == kj + 1) ? 0.0f : ex2f(sacc[nt][3] * scale2);
            l0 += e0 + e1;
            l1 += e2 + e3;
            *reinterpret_cast<float2*>(&Ps[(w * 16 + r    ) * 68 + nt * 8 + 2 * c]) = make_float2(e0, e1);
            *reinterpret_cast<float2*>(&Ps[(w * 16 + r + 8) * 68 + nt * 8 + 2 * c]) = make_float2(e2, e3);
        }
        __syncwarp();

        // O += P V : 8 k-tiles (kv) x 4 n-tiles (d=32). Ps stride 68.
        #pragma unroll
        for (int kt = 0; kt < 8; kt++) {
            uint32_t pa[4];
            {
                const float* p = &Ps[(w * 16 + r) * 68 + kt * 8 + c];
                pa[0] = ldsf(p);       pa[1] = ldsf(p + 544);
                pa[2] = ldsf(p + 4);   pa[3] = ldsf(p + 548);
            }
            #pragma unroll
            for (int nt = 0; nt < 4; nt++) {
                uint32_t vb[2];
                const float* p = &Vs[(kt * 8 + c) * 40 + nt * 8 + r];
                vb[0] = ldsf(p); vb[1] = ldsf(p + 160);   // k+4 rows -> +4*40
                mma_tf32(oacc[nt], pa, vb);
            }
        }
        __syncwarp();   // Ps reads done before next tile overwrites (same warp)
    }

    // reduce l over the 4 lanes of each row group
    #pragma unroll
    for (int off = 1; off < 4; off <<= 1) {
        l0 += __shfl_xor_sync(0xffffffffu, l0, off);
        l1 += __shfl_xor_sync(0xffffffffu, l1, off);
    }
    float inv0 = 1.0f / l0, inv1 = 1.0f / l1;

    int bb = bh >> 3, h = bh & 7;
    int n_0 = q0 + w * 16 + r;
    #pragma unroll
    for (int nt = 0; nt < 4; nt++) {
        int d = nt * 8 + 2 * c;
        size_t base0 = ((size_t)(bb * N_TOK + n_0)) * C_DIM + h * D_HEAD + d;
        size_t base1 = ((size_t)(bb * N_TOK + n_0 + 8)) * C_DIM + h * D_HEAD + d;
        *reinterpret_cast<float2*>(&Outg[base0]) =
            make_float2(oacc[nt][0] * inv0, oacc[nt][1] * inv0);
        *reinterpret_cast<float2*>(&Outg[base1]) =
            make_float2(oacc[nt][2] * inv1, oacc[nt][3] * inv1);
    }
}

// ---------------------------------------------------------------------------
extern "C" void kernel_launch(void* const* d_in, const int* in_sizes, int n_in,
                              void* d_out, int out_size)
{
    const float* x      = (const float*)d_in[0];
    const float* ln1_g  = (const float*)d_in[1];
    const float* ln1_b  = (const float*)d_in[2];
    const float* qkv_w  = (const float*)d_in[3];
    const float* scale  = (const float*)d_in[4];
    const float* proj_w = (const float*)d_in[5];
    const float* proj_b = (const float*)d_in[6];
    const float* ln2_g  = (const float*)d_in[7];
    const float* ln2_b  = (const float*)d_in[8];
    const float* fc1_w  = (const float*)d_in[9];
    const float* fc1_b  = (const float*)d_in[10];
    const float* fc2_w  = (const float*)d_in[11];
    const float* fc2_b  = (const float*)d_in[12];
    float* out = (float*)d_out;

    float *p_xln, *p_qkv, *p_attn, *p_h;
    cudaGetSymbolAddress((void**)&p_xln,  g_xln);
    cudaGetSymbolAddress((void**)&p_qkv,  g_qkv);
    cudaGetSymbolAddress((void**)&p_attn, g_attn);
    cudaGetSymbolAddress((void**)&p_h,    g_h);

    cudaFuncSetAttribute(gemm_mma<EPI_QKV>,
        cudaFuncAttributeMaxDynamicSharedMemorySize, GT_SMEM_BYTES);
    cudaFuncSetAttribute(gemm_mma<EPI_BIAS_RES>,
        cudaFuncAttributeMaxDynamicSharedMemorySize, GT_SMEM_BYTES);
    cudaFuncSetAttribute(gemm_mma<EPI_GELU>,
        cudaFuncAttributeMaxDynamicSharedMemorySize, GT_SMEM_BYTES);
    cudaFuncSetAttribute(attn_mma,
        cudaFuncAttributeMaxDynamicSharedMemorySize, AT_SMEM_BYTES);

    dim3 lnBlock(32, 8);

    // 1. LN1
    ln_kernel<<<M_ROWS / 8, lnBlock>>>(x, ln1_g, ln1_b, p_xln);

    // 2. QKV projection (HMMA tf32) with scatter to (3,B,H,N,D)
    gemm_mma<EPI_QKV><<<dim3(768 / 128, M_ROWS / 128), 256, GT_SMEM_BYTES>>>(
        p_xln, qkv_w, nullptr, nullptr, p_qkv, 768, C_DIM);

    // 3. Attention (HMMA tf32), 128-row Q tiles, cp.async KV pipeline
    attn_mma<<<dim3(N_TOK / 128, B_SZ * H_NUM), 256, AT_SMEM_BYTES>>>(
        p_qkv, p_qkv + BHND, p_qkv + 2 * (size_t)BHND, scale, p_attn);

    // 4. proj + bias + residual -> out
    gemm_mma<EPI_BIAS_RES><<<dim3(C_DIM / 128, M_ROWS / 128), 256, GT_SMEM_BYTES>>>(
        p_attn, proj_w, proj_b, x, out, C_DIM, C_DIM);

    // 5. LN2
    ln_kernel<<<M_ROWS / 8, lnBlock>>>(out, ln2_g, ln2_b, p_xln);

    // 6. fc1 + bias + exact GELU
    gemm_mma<EPI_GELU><<<dim3(HID_D / 128, M_ROWS / 128), 256, GT_SMEM_BYTES>>>(
        p_xln, fc1_w, fc1_b, nullptr, p_h, HID_D, C_DIM);

    // 7. fc2 + bias + residual -> out
    gemm_mma<EPI_BIAS_RES><<<dim3(C_DIM / 128, M_ROWS / 128), 256, GT_SMEM_BYTES>>>(
        p_h, fc2_w, fc2_b, out, out, C_DIM, HID_D);
}